// round 1
// baseline (speedup 1.0000x reference)
#include <cuda_runtime.h>

// ---------------- problem constants (from reference) ----------------
#define NMAX   100000
#define EMAX   1700032
#define NEG_SLOPE 0.2f

// ---------------- scratch (device globals; no allocation allowed) ---
__device__ float g_hlin1[NMAX * 32];   // x @ W1 (pre-bias, pre-relu)
__device__ float g_as1[NMAX];
__device__ float g_ad1[NMAX];
__device__ float g_s1[NMAX];           // softmax denominators, layer 1
__device__ float g_agg1[NMAX * 32];    // layer-1 aggregation
__device__ float g_ex1[EMAX];          // per-edge exp(e), layer 1

__device__ float g_h23[NMAX * 32];     // interleaved: hmu[0..15], hls[0..15]
__device__ float g_asmu[NMAX];
__device__ float g_admu[NMAX];
__device__ float g_asls[NMAX];
__device__ float g_adls[NMAX];
__device__ float g_smu[NMAX];
__device__ float g_sls[NMAX];
__device__ float g_exmu[EMAX];
__device__ float g_exls[EMAX];
__device__ float g_agg23[NMAX * 32];   // interleaved: agg_mu, agg_ls

__device__ int   g_is64;               // 1 if edge_index is int64, 0 if int32

// ---------------- edge index load (dtype detected at runtime) -------
__device__ __forceinline__ void load_edge(const void* __restrict__ ei, int emain,
                                          int e, int n, int& src, int& dst) {
    if (e >= emain) { src = dst = e - emain; return; }
    if (g_is64) {
        const long long* p = (const long long*)ei;
        src = (int)p[e];
        dst = (int)p[emain + e];
    } else {
        const int* p = (const int*)ei;
        src = p[e];
        dst = p[emain + e];
    }
    (void)n;
}

// ---------------- kernels -------------------------------------------

// Detect int32 vs int64 edge_index: for little-endian int64 with values
// < 2^31, every odd 32-bit word is zero. For int32 random indices, odd
// words are ~always nonzero. Probability of misdetection ~ (1e-5)^256.
__global__ void k_detect(const unsigned int* __restrict__ p, int emain) {
    if (blockIdx.x == 0 && threadIdx.x == 0) {
        int cnt = 2 * emain;
        if (cnt > 512) cnt = 512;
        int ok64 = 1;
        for (int i = 1; i < cnt; i += 2)
            if (p[i] != 0u) { ok64 = 0; break; }
        g_is64 = ok64;
    }
}

__global__ void k_zero(int n) {
    int i = blockIdx.x * blockDim.x + threadIdx.x;
    int stride = gridDim.x * blockDim.x;
    for (int j = i; j < n; j += stride) {
        g_s1[j] = 0.0f; g_smu[j] = 0.0f; g_sls[j] = 0.0f;
    }
    int n32 = n * 32;
    for (int j = i; j < n32; j += stride) {
        g_agg1[j] = 0.0f; g_agg23[j] = 0.0f;
    }
}

// hlin1 = x @ W1 ; as1 = hlin1 . a1_src ; ad1 = hlin1 . a1_dst
// One warp per node, lane = output channel (HID=32).
__global__ __launch_bounds__(256) void k_gemm1(
    const float* __restrict__ x, const float* __restrict__ W1,
    const float* __restrict__ a1s, const float* __restrict__ a1d, int n)
{
    __shared__ float Ws[128 * 32];
    __shared__ float xs[8][128];
    __shared__ float asv[32], adv[32];
    int tid = threadIdx.x;
    for (int i = tid; i < 128 * 32; i += 256) Ws[i] = W1[i];
    if (tid < 32) { asv[tid] = a1s[tid]; adv[tid] = a1d[tid]; }
    __syncthreads();
    int warp = tid >> 5, lane = tid & 31;
    for (int node = blockIdx.x * 8 + warp; node < n; node += gridDim.x * 8) {
        const float* xr = x + (size_t)node * 128;
        #pragma unroll
        for (int j = 0; j < 4; j++) xs[warp][lane + 32 * j] = xr[lane + 32 * j];
        __syncwarp();
        float acc = 0.0f;
        #pragma unroll 16
        for (int k = 0; k < 128; k++) acc += xs[warp][k] * Ws[k * 32 + lane];
        g_hlin1[node * 32 + lane] = acc;
        float ts = acc * asv[lane];
        float td = acc * adv[lane];
        #pragma unroll
        for (int off = 16; off >= 1; off >>= 1) {
            ts += __shfl_xor_sync(0xffffffffu, ts, off);
            td += __shfl_xor_sync(0xffffffffu, td, off);
        }
        if (lane == 0) { g_as1[node] = ts; g_ad1[node] = td; }
        __syncwarp();
    }
}

// Layer-1 edge pass A: e -> exp -> store, accumulate denominator.
__global__ __launch_bounds__(256) void k_edgeA1(
    const void* __restrict__ ei, int emain, int n)
{
    int etot = emain + n;
    int stride = gridDim.x * blockDim.x;
    for (int e = blockIdx.x * blockDim.x + threadIdx.x; e < etot; e += stride) {
        int src, dst;
        load_edge(ei, emain, e, n, src, dst);
        float v = g_as1[src] + g_ad1[dst];
        v = (v > 0.0f) ? v : NEG_SLOPE * v;
        float ex = expf(v);
        g_ex1[e] = ex;
        atomicAdd(&g_s1[dst], ex);
    }
}

// Layer-1 edge pass B: warp per edge, lane = channel.
__global__ __launch_bounds__(256) void k_edgeB1(
    const void* __restrict__ ei, int emain, int n)
{
    int etot = emain + n;
    int lane = threadIdx.x & 31;
    int gw = (blockIdx.x * blockDim.x + threadIdx.x) >> 5;
    int nw = (gridDim.x * blockDim.x) >> 5;
    for (int e = gw; e < etot; e += nw) {
        int src, dst;
        load_edge(ei, emain, e, n, src, dst);
        float alpha = g_ex1[e] / g_s1[dst];
        float v = g_hlin1[src * 32 + lane] * alpha;
        atomicAdd(&g_agg1[dst * 32 + lane], v);
    }
}

// h1 = relu(agg1 + b1); h23 = [h1@Wmu | h1@Wls] interleaved; attn dots.
__global__ __launch_bounds__(256) void k_node2(
    const float* __restrict__ b1,
    const float* __restrict__ Wmu, const float* __restrict__ amus,
    const float* __restrict__ amud,
    const float* __restrict__ Wls, const float* __restrict__ alss,
    const float* __restrict__ alsd, int n)
{
    __shared__ float Wmus[32 * 16], Wlss[32 * 16];
    __shared__ float h1s[8][32];
    __shared__ float b1s[32], srcv[32], dstv[32];
    int tid = threadIdx.x;
    for (int i = tid; i < 512; i += 256) { Wmus[i] = Wmu[i]; Wlss[i] = Wls[i]; }
    if (tid < 32) b1s[tid] = b1[tid];
    if (tid < 16)       { srcv[tid] = amus[tid];      dstv[tid] = amud[tid]; }
    else if (tid < 32)  { srcv[tid] = alss[tid - 16]; dstv[tid] = alsd[tid - 16]; }
    __syncthreads();
    int warp = tid >> 5, lane = tid & 31;
    int half = lane >> 4, o = lane & 15;
    const float* Wsel = half ? Wlss : Wmus;
    for (int node = blockIdx.x * 8 + warp; node < n; node += gridDim.x * 8) {
        float v = g_agg1[node * 32 + lane] + b1s[lane];
        v = (v > 0.0f) ? v : 0.0f;   // relu
        h1s[warp][lane] = v;
        __syncwarp();
        float acc = 0.0f;
        #pragma unroll
        for (int c = 0; c < 32; c++) acc += h1s[warp][c] * Wsel[c * 16 + o];
        g_h23[node * 32 + lane] = acc;
        float ts = acc * srcv[lane];
        float td = acc * dstv[lane];
        #pragma unroll
        for (int off = 8; off >= 1; off >>= 1) {
            ts += __shfl_xor_sync(0xffffffffu, ts, off);
            td += __shfl_xor_sync(0xffffffffu, td, off);
        }
        if (o == 0) {
            if (half == 0) { g_asmu[node] = ts; g_admu[node] = td; }
            else           { g_asls[node] = ts; g_adls[node] = td; }
        }
        __syncwarp();
    }
}

// Fused mu+logstd edge pass A.
__global__ __launch_bounds__(256) void k_edgeA23(
    const void* __restrict__ ei, int emain, int n)
{
    int etot = emain + n;
    int stride = gridDim.x * blockDim.x;
    for (int e = blockIdx.x * blockDim.x + threadIdx.x; e < etot; e += stride) {
        int src, dst;
        load_edge(ei, emain, e, n, src, dst);
        float vmu = g_asmu[src] + g_admu[dst];
        vmu = (vmu > 0.0f) ? vmu : NEG_SLOPE * vmu;
        float exmu = expf(vmu);
        g_exmu[e] = exmu;
        atomicAdd(&g_smu[dst], exmu);

        float vls = g_asls[src] + g_adls[dst];
        vls = (vls > 0.0f) ? vls : NEG_SLOPE * vls;
        float exls = expf(vls);
        g_exls[e] = exls;
        atomicAdd(&g_sls[dst], exls);
    }
}

// Fused mu+logstd edge pass B: warp per edge; lanes 0..15 mu, 16..31 ls.
__global__ __launch_bounds__(256) void k_edgeB23(
    const void* __restrict__ ei, int emain, int n)
{
    int etot = emain + n;
    int lane = threadIdx.x & 31;
    int gw = (blockIdx.x * blockDim.x + threadIdx.x) >> 5;
    int nw = (gridDim.x * blockDim.x) >> 5;
    for (int e = gw; e < etot; e += nw) {
        int src, dst;
        load_edge(ei, emain, e, n, src, dst);
        float alpha = (lane < 16) ? (g_exmu[e] / g_smu[dst])
                                  : (g_exls[e] / g_sls[dst]);
        float v = g_h23[src * 32 + lane] * alpha;
        atomicAdd(&g_agg23[dst * 32 + lane], v);
    }
}

// Split interleaved agg into (mu | logstd) halves of d_out, add biases.
__global__ __launch_bounds__(256) void k_final(
    const float* __restrict__ bmu, const float* __restrict__ bls,
    float* __restrict__ out, int n)
{
    int total = n * 16;
    int stride = gridDim.x * blockDim.x;
    for (int i = blockIdx.x * blockDim.x + threadIdx.x; i < total; i += stride) {
        int node = i >> 4, c = i & 15;
        out[i]         = g_agg23[node * 32 + c]      + bmu[c];
        out[total + i] = g_agg23[node * 32 + 16 + c] + bls[c];
    }
}

// ---------------- launch ---------------------------------------------
extern "C" void kernel_launch(void* const* d_in, const int* in_sizes, int n_in,
                              void* d_out, int out_size)
{
    const float* x    = (const float*)d_in[0];
    const void*  ei   = d_in[1];
    const float* W1   = (const float*)d_in[2];
    const float* a1s  = (const float*)d_in[3];
    const float* a1d  = (const float*)d_in[4];
    const float* b1   = (const float*)d_in[5];
    const float* Wmu  = (const float*)d_in[6];
    const float* amus = (const float*)d_in[7];
    const float* amud = (const float*)d_in[8];
    const float* bmu  = (const float*)d_in[9];
    const float* Wls  = (const float*)d_in[10];
    const float* alss = (const float*)d_in[11];
    const float* alsd = (const float*)d_in[12];
    const float* bls  = (const float*)d_in[13];

    int n     = in_sizes[0] / 128;      // 100000
    int emain = in_sizes[1] / 2;        // 1600000
    int etot  = emain + n;
    float* out = (float*)d_out;

    k_detect<<<1, 32>>>((const unsigned int*)ei, emain);
    k_zero<<<2048, 256>>>(n);
    k_gemm1<<<(n + 7) / 8, 256>>>(x, W1, a1s, a1d, n);
    k_edgeA1<<<(etot + 255) / 256, 256>>>(ei, emain, n);
    k_edgeB1<<<(etot + 7) / 8, 256>>>(ei, emain, n);
    k_node2<<<(n + 7) / 8, 256>>>(b1, Wmu, amus, amud, Wls, alss, alsd, n);
    k_edgeA23<<<(etot + 255) / 256, 256>>>(ei, emain, n);
    k_edgeB23<<<(etot + 7) / 8, 256>>>(ei, emain, n);
    k_final<<<2048, 256>>>(bmu, bls, out, n);
}

// round 2
// speedup vs baseline: 2.4374x; 2.4374x over previous
#include <cuda_runtime.h>

// ---------------- problem constants (from reference) ----------------
#define NMAX   100000
#define EMAX   1700032
#define NEG_SLOPE 0.2f

// ---------------- scratch (device globals; no allocation allowed) ---
__device__ __align__(16) float g_hlin1[NMAX * 32];   // x @ W1 (pre-bias, pre-relu)
__device__ float g_as1[NMAX];
__device__ float g_ad1[NMAX];
__device__ float g_s1[NMAX];                         // denom -> inverse, layer 1
__device__ __align__(16) float g_agg1[NMAX * 32];    // layer-1 aggregation
__device__ float g_ex1[EMAX];                        // per-edge exp(e), layer 1

__device__ __align__(16) float g_h23[NMAX * 32];     // interleaved: hmu[0..15], hls[0..15]
__device__ __align__(8)  float g_src23[NMAX * 2];    // {asmu, asls} per node
__device__ __align__(8)  float g_dst23[NMAX * 2];    // {admu, adls} per node
__device__ __align__(8)  float g_s23[NMAX * 2];      // {smu, sls} denom -> inverse
__device__ __align__(8)  float g_ex23[EMAX * 2];     // {exmu, exls} per edge
__device__ __align__(16) float g_agg23[NMAX * 32];   // interleaved: agg_mu, agg_ls

__device__ __align__(8)  int2  g_edges[EMAX];        // decoded (src,dst), incl self-loops
__device__ int   g_is64;                             // 1 if edge_index is int64

// ---------------- kernels -------------------------------------------

// Detect int32 vs int64 edge_index: for little-endian int64 with values
// < 2^31, every odd 32-bit word is zero. Parallel across 256 threads.
__global__ void k_detect(const unsigned int* __restrict__ p, int emain) {
    __shared__ int bad;
    if (threadIdx.x == 0) bad = 0;
    __syncthreads();
    int cnt = 2 * emain; if (cnt > 8192) cnt = 8192;
    for (int i = 1 + 2 * threadIdx.x; i < cnt; i += 2 * blockDim.x)
        if (p[i] != 0u) bad = 1;
    __syncthreads();
    if (threadIdx.x == 0) g_is64 = bad ? 0 : 1;
}

// Decode edge_index (either dtype) + append self-loops into packed int2.
__global__ __launch_bounds__(256) void k_convert(const void* __restrict__ ei,
                                                 int emain, int n) {
    int etot = emain + n;
    int stride = gridDim.x * blockDim.x;
    int is64 = g_is64;
    for (int e = blockIdx.x * blockDim.x + threadIdx.x; e < etot; e += stride) {
        int s, d;
        if (e >= emain) { s = d = e - emain; }
        else if (is64) {
            const long long* p = (const long long*)ei;
            s = (int)p[e]; d = (int)p[emain + e];
        } else {
            const int* p = (const int*)ei;
            s = p[e]; d = p[emain + e];
        }
        g_edges[e] = make_int2(s, d);
    }
}

__global__ void k_zero(int n) {
    int i = blockIdx.x * blockDim.x + threadIdx.x;
    int stride = gridDim.x * blockDim.x;
    for (int j = i; j < n; j += stride) g_s1[j] = 0.0f;
    for (int j = i; j < 2 * n; j += stride) g_s23[j] = 0.0f;
    int n32 = n * 32;
    for (int j = i; j < n32; j += stride) {
        g_agg1[j] = 0.0f; g_agg23[j] = 0.0f;
    }
}

// hlin1 = x @ W1 ; as1 = hlin1 . a1_src ; ad1 = hlin1 . a1_dst
__global__ __launch_bounds__(256) void k_gemm1(
    const float* __restrict__ x, const float* __restrict__ W1,
    const float* __restrict__ a1s, const float* __restrict__ a1d, int n)
{
    __shared__ float Ws[128 * 32];
    __shared__ float xs[8][128];
    __shared__ float asv[32], adv[32];
    int tid = threadIdx.x;
    for (int i = tid; i < 128 * 32; i += 256) Ws[i] = W1[i];
    if (tid < 32) { asv[tid] = a1s[tid]; adv[tid] = a1d[tid]; }
    __syncthreads();
    int warp = tid >> 5, lane = tid & 31;
    for (int node = blockIdx.x * 8 + warp; node < n; node += gridDim.x * 8) {
        const float* xr = x + (size_t)node * 128;
        #pragma unroll
        for (int j = 0; j < 4; j++) xs[warp][lane + 32 * j] = xr[lane + 32 * j];
        __syncwarp();
        float acc = 0.0f;
        #pragma unroll 16
        for (int k = 0; k < 128; k++) acc += xs[warp][k] * Ws[k * 32 + lane];
        g_hlin1[node * 32 + lane] = acc;
        float ts = acc * asv[lane];
        float td = acc * adv[lane];
        #pragma unroll
        for (int off = 16; off >= 1; off >>= 1) {
            ts += __shfl_xor_sync(0xffffffffu, ts, off);
            td += __shfl_xor_sync(0xffffffffu, td, off);
        }
        if (lane == 0) { g_as1[node] = ts; g_ad1[node] = td; }
        __syncwarp();
    }
}

// Layer-1 edge pass A: e -> exp -> store, accumulate denominator.
__global__ __launch_bounds__(256) void k_edgeA1(int etot)
{
    int stride = gridDim.x * blockDim.x;
    for (int e = blockIdx.x * blockDim.x + threadIdx.x; e < etot; e += stride) {
        int2 ed = g_edges[e];
        float v = g_as1[ed.x] + g_ad1[ed.y];
        v = (v > 0.0f) ? v : NEG_SLOPE * v;
        float ex = __expf(v);
        g_ex1[e] = ex;
        atomicAdd(&g_s1[ed.y], ex);
    }
}

__global__ void k_recip1(int n) {
    int i = blockIdx.x * blockDim.x + threadIdx.x;
    if (i < n) g_s1[i] = __frcp_rn(g_s1[i]);
}

// Layer-1 edge pass B: 8 lanes per edge, one float4 vector RED per lane.
__global__ __launch_bounds__(256) void k_edgeB1(int etot)
{
    int t = blockIdx.x * blockDim.x + threadIdx.x;
    int e = t >> 3;
    if (e >= etot) return;
    int q = t & 7;
    int2 ed = g_edges[e];
    float alpha = g_ex1[e] * g_s1[ed.y];   // g_s1 holds 1/denominator
    const float4* hp = (const float4*)(g_hlin1 + ed.x * 32);
    float4 h = hp[q];
    float4 v = make_float4(h.x * alpha, h.y * alpha, h.z * alpha, h.w * alpha);
    float* dp = g_agg1 + ed.y * 32 + q * 4;
    asm volatile("red.global.add.v4.f32 [%0], {%1,%2,%3,%4};"
                 :: "l"(dp), "f"(v.x), "f"(v.y), "f"(v.z), "f"(v.w) : "memory");
}

// h1 = relu(agg1 + b1); h23 = [h1@Wmu | h1@Wls] interleaved; attn dots.
__global__ __launch_bounds__(256) void k_node2(
    const float* __restrict__ b1,
    const float* __restrict__ Wmu, const float* __restrict__ amus,
    const float* __restrict__ amud,
    const float* __restrict__ Wls, const float* __restrict__ alss,
    const float* __restrict__ alsd, int n)
{
    __shared__ float Wmus[32 * 16], Wlss[32 * 16];
    __shared__ float h1s[8][32];
    __shared__ float b1s[32], srcv[32], dstv[32];
    int tid = threadIdx.x;
    for (int i = tid; i < 512; i += 256) { Wmus[i] = Wmu[i]; Wlss[i] = Wls[i]; }
    if (tid < 32) b1s[tid] = b1[tid];
    if (tid < 16)       { srcv[tid] = amus[tid];      dstv[tid] = amud[tid]; }
    else if (tid < 32)  { srcv[tid] = alss[tid - 16]; dstv[tid] = alsd[tid - 16]; }
    __syncthreads();
    int warp = tid >> 5, lane = tid & 31;
    int half = lane >> 4, o = lane & 15;
    const float* Wsel = half ? Wlss : Wmus;
    for (int node = blockIdx.x * 8 + warp; node < n; node += gridDim.x * 8) {
        float v = g_agg1[node * 32 + lane] + b1s[lane];
        v = (v > 0.0f) ? v : 0.0f;   // relu
        h1s[warp][lane] = v;
        __syncwarp();
        float acc = 0.0f;
        #pragma unroll
        for (int c = 0; c < 32; c++) acc += h1s[warp][c] * Wsel[c * 16 + o];
        g_h23[node * 32 + lane] = acc;
        float ts = acc * srcv[lane];
        float td = acc * dstv[lane];
        #pragma unroll
        for (int off = 8; off >= 1; off >>= 1) {
            ts += __shfl_xor_sync(0xffffffffu, ts, off);
            td += __shfl_xor_sync(0xffffffffu, td, off);
        }
        if (o == 0) {
            // interleave {mu, ls} per node for float2 gathers in edge passes
            g_src23[2 * node + half] = ts;
            g_dst23[2 * node + half] = td;
        }
        __syncwarp();
    }
}

// Fused mu+logstd edge pass A: float2 gathers + one v2 vector RED.
__global__ __launch_bounds__(256) void k_edgeA23(int etot)
{
    int stride = gridDim.x * blockDim.x;
    for (int e = blockIdx.x * blockDim.x + threadIdx.x; e < etot; e += stride) {
        int2 ed = g_edges[e];
        float2 sv = *(const float2*)(g_src23 + 2 * ed.x);
        float2 dv = *(const float2*)(g_dst23 + 2 * ed.y);
        float vmu = sv.x + dv.x;
        float vls = sv.y + dv.y;
        vmu = (vmu > 0.0f) ? vmu : NEG_SLOPE * vmu;
        vls = (vls > 0.0f) ? vls : NEG_SLOPE * vls;
        float exmu = __expf(vmu);
        float exls = __expf(vls);
        *(float2*)(g_ex23 + 2 * e) = make_float2(exmu, exls);
        float* dp = g_s23 + 2 * ed.y;
        asm volatile("red.global.add.v2.f32 [%0], {%1,%2};"
                     :: "l"(dp), "f"(exmu), "f"(exls) : "memory");
    }
}

__global__ void k_recip23(int n) {
    int i = blockIdx.x * blockDim.x + threadIdx.x;
    if (i < 2 * n) g_s23[i] = __frcp_rn(g_s23[i]);
}

// Fused mu+logstd edge pass B: 8 lanes/edge; q<4 handles mu, q>=4 ls.
__global__ __launch_bounds__(256) void k_edgeB23(int etot)
{
    int t = blockIdx.x * blockDim.x + threadIdx.x;
    int e = t >> 3;
    if (e >= etot) return;
    int q = t & 7;
    int2 ed = g_edges[e];
    float2 ex  = *(const float2*)(g_ex23 + 2 * e);
    float2 inv = *(const float2*)(g_s23  + 2 * ed.y);
    float alpha = (q < 4) ? ex.x * inv.x : ex.y * inv.y;
    const float4* hp = (const float4*)(g_h23 + ed.x * 32);
    float4 h = hp[q];
    float4 v = make_float4(h.x * alpha, h.y * alpha, h.z * alpha, h.w * alpha);
    float* dp = g_agg23 + ed.y * 32 + q * 4;
    asm volatile("red.global.add.v4.f32 [%0], {%1,%2,%3,%4};"
                 :: "l"(dp), "f"(v.x), "f"(v.y), "f"(v.z), "f"(v.w) : "memory");
}

// Split interleaved agg into (mu | logstd) halves of d_out, add biases.
__global__ __launch_bounds__(256) void k_final(
    const float* __restrict__ bmu, const float* __restrict__ bls,
    float* __restrict__ out, int n)
{
    int total = n * 16;
    int stride = gridDim.x * blockDim.x;
    for (int i = blockIdx.x * blockDim.x + threadIdx.x; i < total; i += stride) {
        int node = i >> 4, c = i & 15;
        out[i]         = g_agg23[node * 32 + c]      + bmu[c];
        out[total + i] = g_agg23[node * 32 + 16 + c] + bls[c];
    }
}

// ---------------- launch ---------------------------------------------
extern "C" void kernel_launch(void* const* d_in, const int* in_sizes, int n_in,
                              void* d_out, int out_size)
{
    const float* x    = (const float*)d_in[0];
    const void*  ei   = d_in[1];
    const float* W1   = (const float*)d_in[2];
    const float* a1s  = (const float*)d_in[3];
    const float* a1d  = (const float*)d_in[4];
    const float* b1   = (const float*)d_in[5];
    const float* Wmu  = (const float*)d_in[6];
    const float* amus = (const float*)d_in[7];
    const float* amud = (const float*)d_in[8];
    const float* bmu  = (const float*)d_in[9];
    const float* Wls  = (const float*)d_in[10];
    const float* alss = (const float*)d_in[11];
    const float* alsd = (const float*)d_in[12];
    const float* bls  = (const float*)d_in[13];

    int n     = in_sizes[0] / 128;      // 100000
    int emain = in_sizes[1] / 2;        // 1600000
    int etot  = emain + n;
    float* out = (float*)d_out;

    k_detect<<<1, 256>>>((const unsigned int*)ei, emain);
    k_convert<<<2048, 256>>>(ei, emain, n);
    k_zero<<<2048, 256>>>(n);
    k_gemm1<<<(n + 7) / 8, 256>>>(x, W1, a1s, a1d, n);
    k_edgeA1<<<(etot + 255) / 256, 256>>>(etot);
    k_recip1<<<(n + 255) / 256, 256>>>(n);
    k_edgeB1<<<(etot * 8 + 255) / 256, 256>>>(etot);
    k_node2<<<(n + 7) / 8, 256>>>(b1, Wmu, amus, amud, Wls, alss, alsd, n);
    k_edgeA23<<<(etot + 255) / 256, 256>>>(etot);
    k_recip23<<<(2 * n + 255) / 256, 256>>>(n);
    k_edgeB23<<<(etot * 8 + 255) / 256, 256>>>(etot);
    k_final<<<2048, 256>>>(bmu, bls, out, n);
}

// round 4
// speedup vs baseline: 2.9563x; 1.2129x over previous
#include <cuda_runtime.h>

// ---------------- problem constants (from reference) ----------------
#define NMAX   100000
#define EMAX   1700032
#define NEG_SLOPE 0.2f

__device__ __forceinline__ void fma4(float4& acc, float s, const float4& wv) {
    acc.x = fmaf(s, wv.x, acc.x); acc.y = fmaf(s, wv.y, acc.y);
    acc.z = fmaf(s, wv.z, acc.z); acc.w = fmaf(s, wv.w, acc.w);
}

// ---------------- scratch (device globals; no allocation allowed) ---
__device__ __align__(16) float g_hlin1[NMAX * 32];   // x @ W1 (pre-bias, pre-relu)
__device__ float g_as1[NMAX];
__device__ float g_ad1[NMAX];
__device__ float g_s1[NMAX];                         // denom -> inverse, layer 1
__device__ __align__(16) float g_agg1[NMAX * 32];    // layer-1 aggregation
__device__ float g_ex1[EMAX];                        // per-edge exp(e), layer 1

__device__ __align__(16) float g_h23[NMAX * 32];     // interleaved: hmu[0..15], hls[0..15]
__device__ __align__(8)  float g_src23[NMAX * 2];    // {asmu, asls} per node
__device__ __align__(8)  float g_dst23[NMAX * 2];    // {admu, adls} per node
__device__ __align__(8)  float g_s23[NMAX * 2];      // {smu, sls} denom -> inverse
__device__ __align__(8)  float g_ex23[EMAX * 2];     // {exmu, exls} per edge
__device__ __align__(16) float g_agg23[NMAX * 32];   // interleaved: agg_mu, agg_ls

__device__ __align__(8)  int2  g_edges[EMAX];        // decoded (src,dst), incl self-loops
__device__ int   g_is64;                             // 1 if edge_index is int64

// ---------------- kernels -------------------------------------------

__global__ void k_detect(const unsigned int* __restrict__ p, int emain) {
    __shared__ int bad;
    if (threadIdx.x == 0) bad = 0;
    __syncthreads();
    int cnt = 2 * emain; if (cnt > 8192) cnt = 8192;
    for (int i = 1 + 2 * threadIdx.x; i < cnt; i += 2 * blockDim.x)
        if (p[i] != 0u) bad = 1;
    __syncthreads();
    if (threadIdx.x == 0) g_is64 = bad ? 0 : 1;
}

__global__ __launch_bounds__(256) void k_convert(const void* __restrict__ ei,
                                                 int emain, int n) {
    int etot = emain + n;
    int stride = gridDim.x * blockDim.x;
    int is64 = g_is64;
    for (int e = blockIdx.x * blockDim.x + threadIdx.x; e < etot; e += stride) {
        int s, d;
        if (e >= emain) { s = d = e - emain; }
        else if (is64) {
            const long long* p = (const long long*)ei;
            s = (int)p[e]; d = (int)p[emain + e];
        } else {
            const int* p = (const int*)ei;
            s = p[e]; d = p[emain + e];
        }
        g_edges[e] = make_int2(s, d);
    }
}

__global__ void k_zero(int n) {
    int i = blockIdx.x * blockDim.x + threadIdx.x;
    int stride = gridDim.x * blockDim.x;
    for (int j = i; j < n; j += stride) g_s1[j] = 0.0f;
    for (int j = i; j < 2 * n; j += stride) g_s23[j] = 0.0f;
    int n32 = n * 32;
    for (int j = i; j < n32; j += stride) {
        g_agg1[j] = 0.0f; g_agg23[j] = 0.0f;
    }
}

// hlin1 = x @ W1 ; as1/ad1 attention dots. 8 threads per node, vectorized.
__global__ __launch_bounds__(256) void k_gemm1(
    const float* __restrict__ x, const float* __restrict__ W1,
    const float* __restrict__ a1s, const float* __restrict__ a1d, int n)
{
    __shared__ float4 Ws4[128 * 8];    // [k][q] = W1[k][4q..4q+3]
    __shared__ float4 xs4[32 * 33];    // 32 nodes x (32 float4 + 1 pad)
    __shared__ float4 as4[8], ad4[8];
    int tid = threadIdx.x;
    const float4* W4 = (const float4*)W1;
    for (int i = tid; i < 1024; i += 256) Ws4[i] = W4[i];
    if (tid < 8)        as4[tid]     = ((const float4*)a1s)[tid];
    else if (tid < 16)  ad4[tid - 8] = ((const float4*)a1d)[tid - 8];

    int base = blockIdx.x * 32;
    // stage 32 nodes of x, coalesced
    const float4* xg = (const float4*)x + (size_t)base * 32;
    int navail = n - base; if (navail > 32) navail = 32;
    for (int f = tid; f < navail * 32; f += 256) {
        int node = f >> 5, j = f & 31;
        xs4[node * 33 + j] = xg[f];
    }
    __syncthreads();

    int warp = tid >> 5, lane = tid & 31;
    int nsub = lane >> 3, q = lane & 7;
    int nodeL = warp * 4 + nsub;
    int node = base + nodeL;
    if (node >= n) return;

    const float4* xr = xs4 + nodeL * 33;
    float4 acc = make_float4(0.f, 0.f, 0.f, 0.f);
    #pragma unroll 4
    for (int k4 = 0; k4 < 32; k4++) {
        float4 xv = xr[k4];
        float4 w0 = Ws4[(k4 * 4 + 0) * 8 + q];
        float4 w1 = Ws4[(k4 * 4 + 1) * 8 + q];
        float4 w2 = Ws4[(k4 * 4 + 2) * 8 + q];
        float4 w3 = Ws4[(k4 * 4 + 3) * 8 + q];
        fma4(acc, xv.x, w0); fma4(acc, xv.y, w1);
        fma4(acc, xv.z, w2); fma4(acc, xv.w, w3);
    }
    ((float4*)(g_hlin1 + (size_t)node * 32))[q] = acc;

    float4 av = as4[q], dv = ad4[q];
    float ts = acc.x * av.x + acc.y * av.y + acc.z * av.z + acc.w * av.w;
    float td = acc.x * dv.x + acc.y * dv.y + acc.z * dv.z + acc.w * dv.w;
    #pragma unroll
    for (int off = 4; off >= 1; off >>= 1) {
        ts += __shfl_xor_sync(0xffffffffu, ts, off);
        td += __shfl_xor_sync(0xffffffffu, td, off);
    }
    if (q == 0) { g_as1[node] = ts; g_ad1[node] = td; }
}

// Layer-1 edge pass A.
__global__ __launch_bounds__(256) void k_edgeA1(int etot)
{
    int stride = gridDim.x * blockDim.x;
    for (int e = blockIdx.x * blockDim.x + threadIdx.x; e < etot; e += stride) {
        int2 ed = g_edges[e];
        float v = g_as1[ed.x] + g_ad1[ed.y];
        v = (v > 0.0f) ? v : NEG_SLOPE * v;
        float ex = __expf(v);
        g_ex1[e] = ex;
        atomicAdd(&g_s1[ed.y], ex);
    }
}

__global__ void k_recip1(int n) {
    int i = blockIdx.x * blockDim.x + threadIdx.x;
    if (i < n) g_s1[i] = __frcp_rn(g_s1[i]);
}

// Layer-1 edge pass B: 8 lanes per edge, one float4 vector RED per lane.
__global__ __launch_bounds__(256) void k_edgeB1(int etot)
{
    int t = blockIdx.x * blockDim.x + threadIdx.x;
    int e = t >> 3;
    if (e >= etot) return;
    int q = t & 7;
    int2 ed = g_edges[e];
    float alpha = g_ex1[e] * g_s1[ed.y];
    const float4* hp = (const float4*)(g_hlin1 + (size_t)ed.x * 32);
    float4 h = hp[q];
    float4 v = make_float4(h.x * alpha, h.y * alpha, h.z * alpha, h.w * alpha);
    float* dp = g_agg1 + (size_t)ed.y * 32 + q * 4;
    asm volatile("red.global.add.v4.f32 [%0], {%1,%2,%3,%4};"
                 :: "l"(dp), "f"(v.x), "f"(v.y), "f"(v.z), "f"(v.w) : "memory");
}

// h1 = relu(agg1+b1); h23 = h1 @ [Wmu|Wls] interleaved; attn dots. Vectorized.
__global__ __launch_bounds__(256) void k_node2(
    const float* __restrict__ b1,
    const float* __restrict__ Wmu, const float* __restrict__ amus,
    const float* __restrict__ amud,
    const float* __restrict__ Wls, const float* __restrict__ alss,
    const float* __restrict__ alsd, int n)
{
    __shared__ float Wcat[32 * 32];      // [k][c]: c<16 mu, c>=16 ls
    __shared__ float4 h1s4[32 * 9];      // 32 nodes x (8 float4 + 1 pad)
    __shared__ float4 b1s4[8];
    __shared__ float4 srcv4[8], dstv4[8];
    int tid = threadIdx.x;
    for (int i = tid; i < 1024; i += 256) {
        int k = i >> 5, c = i & 31;
        Wcat[i] = (c < 16) ? Wmu[k * 16 + c] : Wls[k * 16 + (c - 16)];
    }
    if (tid < 8) b1s4[tid] = ((const float4*)b1)[tid];
    if (tid < 32) {
        float sv = (tid < 16) ? amus[tid] : alss[tid - 16];
        float dv = (tid < 16) ? amud[tid] : alsd[tid - 16];
        ((float*)srcv4)[tid] = sv;
        ((float*)dstv4)[tid] = dv;
    }
    __syncthreads();

    int warp = tid >> 5, lane = tid & 31;
    int nsub = lane >> 3, q = lane & 7;
    int nodeL = warp * 4 + nsub;
    int node = blockIdx.x * 32 + nodeL;
    if (node >= n) return;

    // compute h1 (this group's 4 channels), stage to smem
    float4 a = ((const float4*)(g_agg1 + (size_t)node * 32))[q];
    float4 bb = b1s4[q];
    float4 h;
    h.x = fmaxf(a.x + bb.x, 0.f); h.y = fmaxf(a.y + bb.y, 0.f);
    h.z = fmaxf(a.z + bb.z, 0.f); h.w = fmaxf(a.w + bb.w, 0.f);
    h1s4[nodeL * 9 + q] = h;
    __syncwarp();

    const float4* hr = h1s4 + nodeL * 9;
    const float4* Wc4 = (const float4*)Wcat;
    float4 acc = make_float4(0.f, 0.f, 0.f, 0.f);
    #pragma unroll
    for (int k4 = 0; k4 < 8; k4++) {
        float4 hv = hr[k4];
        float4 w0 = Wc4[(k4 * 4 + 0) * 8 + q];
        float4 w1 = Wc4[(k4 * 4 + 1) * 8 + q];
        float4 w2 = Wc4[(k4 * 4 + 2) * 8 + q];
        float4 w3 = Wc4[(k4 * 4 + 3) * 8 + q];
        fma4(acc, hv.x, w0); fma4(acc, hv.y, w1);
        fma4(acc, hv.z, w2); fma4(acc, hv.w, w3);
    }
    ((float4*)(g_h23 + (size_t)node * 32))[q] = acc;

    float4 av = srcv4[q], dv = dstv4[q];
    float ts = acc.x * av.x + acc.y * av.y + acc.z * av.z + acc.w * av.w;
    float td = acc.x * dv.x + acc.y * dv.y + acc.z * dv.z + acc.w * dv.w;
    #pragma unroll
    for (int off = 2; off >= 1; off >>= 1) {   // reduce within 4-lane half
        ts += __shfl_xor_sync(0xffffffffu, ts, off);
        td += __shfl_xor_sync(0xffffffffu, td, off);
    }
    if (q == 0) { g_src23[2 * node + 0] = ts; g_dst23[2 * node + 0] = td; }
    if (q == 4) { g_src23[2 * node + 1] = ts; g_dst23[2 * node + 1] = td; }
}

// Fused mu+logstd edge pass A.
__global__ __launch_bounds__(256) void k_edgeA23(int etot)
{
    int stride = gridDim.x * blockDim.x;
    for (int e = blockIdx.x * blockDim.x + threadIdx.x; e < etot; e += stride) {
        int2 ed = g_edges[e];
        float2 sv = *(const float2*)(g_src23 + 2 * ed.x);
        float2 dv = *(const float2*)(g_dst23 + 2 * ed.y);
        float vmu = sv.x + dv.x;
        float vls = sv.y + dv.y;
        vmu = (vmu > 0.0f) ? vmu : NEG_SLOPE * vmu;
        vls = (vls > 0.0f) ? vls : NEG_SLOPE * vls;
        float exmu = __expf(vmu);
        float exls = __expf(vls);
        *(float2*)(g_ex23 + 2 * e) = make_float2(exmu, exls);
        float* dp = g_s23 + 2 * ed.y;
        asm volatile("red.global.add.v2.f32 [%0], {%1,%2};"
                     :: "l"(dp), "f"(exmu), "f"(exls) : "memory");
    }
}

__global__ void k_recip23(int n) {
    int i = blockIdx.x * blockDim.x + threadIdx.x;
    if (i < 2 * n) g_s23[i] = __frcp_rn(g_s23[i]);
}

// Fused mu+logstd edge pass B.
__global__ __launch_bounds__(256) void k_edgeB23(int etot)
{
    int t = blockIdx.x * blockDim.x + threadIdx.x;
    int e = t >> 3;
    if (e >= etot) return;
    int q = t & 7;
    int2 ed = g_edges[e];
    float2 ex  = *(const float2*)(g_ex23 + 2 * e);
    float2 inv = *(const float2*)(g_s23  + 2 * ed.y);
    float alpha = (q < 4) ? ex.x * inv.x : ex.y * inv.y;
    const float4* hp = (const float4*)(g_h23 + (size_t)ed.x * 32);
    float4 h = hp[q];
    float4 v = make_float4(h.x * alpha, h.y * alpha, h.z * alpha, h.w * alpha);
    float* dp = g_agg23 + (size_t)ed.y * 32 + q * 4;
    asm volatile("red.global.add.v4.f32 [%0], {%1,%2,%3,%4};"
                 :: "l"(dp), "f"(v.x), "f"(v.y), "f"(v.z), "f"(v.w) : "memory");
}

// Split interleaved agg into (mu | logstd) halves of d_out, add biases.
__global__ __launch_bounds__(256) void k_final(
    const float* __restrict__ bmu, const float* __restrict__ bls,
    float* __restrict__ out, int n)
{
    int total = n * 16;
    int stride = gridDim.x * blockDim.x;
    for (int i = blockIdx.x * blockDim.x + threadIdx.x; i < total; i += stride) {
        int node = i >> 4, c = i & 15;
        out[i]         = g_agg23[node * 32 + c]      + bmu[c];
        out[total + i] = g_agg23[node * 32 + 16 + c] + bls[c];
    }
}

// ---------------- launch ---------------------------------------------
extern "C" void kernel_launch(void* const* d_in, const int* in_sizes, int n_in,
                              void* d_out, int out_size)
{
    const float* x    = (const float*)d_in[0];
    const void*  ei   = d_in[1];
    const float* W1   = (const float*)d_in[2];
    const float* a1s  = (const float*)d_in[3];
    const float* a1d  = (const float*)d_in[4];
    const float* b1   = (const float*)d_in[5];
    const float* Wmu  = (const float*)d_in[6];
    const float* amus = (const float*)d_in[7];
    const float* amud = (const float*)d_in[8];
    const float* bmu  = (const float*)d_in[9];
    const float* Wls  = (const float*)d_in[10];
    const float* alss = (const float*)d_in[11];
    const float* alsd = (const float*)d_in[12];
    const float* bls  = (const float*)d_in[13];

    int n     = in_sizes[0] / 128;      // 100000
    int emain = in_sizes[1] / 2;        // 1600000
    int etot  = emain + n;
    float* out = (float*)d_out;

    k_detect<<<1, 256>>>((const unsigned int*)ei, emain);
    k_convert<<<2048, 256>>>(ei, emain, n);
    k_zero<<<2048, 256>>>(n);
    k_gemm1<<<(n + 31) / 32, 256>>>(x, W1, a1s, a1d, n);
    k_edgeA1<<<(etot + 255) / 256, 256>>>(etot);
    k_recip1<<<(n + 255) / 256, 256>>>(n);
    k_edgeB1<<<(etot * 8 + 255) / 256, 256>>>(etot);
    k_node2<<<(n + 31) / 32, 256>>>(b1, Wmu, amus, amud, Wls, alss, alsd, n);
    k_edgeA23<<<(etot + 255) / 256, 256>>>(etot);
    k_recip23<<<(2 * n + 255) / 256, 256>>>(n);
    k_edgeB23<<<(etot * 8 + 255) / 256, 256>>>(etot);
    k_final<<<2048, 256>>>(bmu, bls, out, n);
}

// round 5
// speedup vs baseline: 3.2535x; 1.1005x over previous
#include <cuda_runtime.h>

// ---------------- problem constants (from reference) ----------------
#define NMAX   100000
#define EMAX   1700032
#define NEG_SLOPE 0.2f

__device__ __forceinline__ void fma4(float4& acc, float s, const float4& wv) {
    acc.x = fmaf(s, wv.x, acc.x); acc.y = fmaf(s, wv.y, acc.y);
    acc.z = fmaf(s, wv.z, acc.z); acc.w = fmaf(s, wv.w, acc.w);
}

// ---------------- scratch (device globals; no allocation allowed) ---
__device__ __align__(16) float g_hlin1[NMAX * 32];
__device__ float g_as1[NMAX];
__device__ float g_ad1[NMAX];
__device__ float g_s1[NMAX];                         // denom -> inverse
__device__ __align__(16) float g_agg1[NMAX * 32];
__device__ float g_ex1[EMAX];

__device__ __align__(16) float g_h23[NMAX * 32];     // interleaved mu|ls
__device__ __align__(8)  float g_src23[NMAX * 2];
__device__ __align__(8)  float g_dst23[NMAX * 2];
__device__ __align__(8)  float g_s23[NMAX * 2];
__device__ __align__(8)  float g_ex23[EMAX * 2];
__device__ __align__(16) float g_agg23[NMAX * 32];

__device__ __align__(8)  int2  g_edges[EMAX];
__device__ int   g_is64;

// ---------------- kernels -------------------------------------------

__global__ void k_detect(const unsigned int* __restrict__ p, int emain) {
    __shared__ int bad;
    if (threadIdx.x == 0) bad = 0;
    __syncthreads();
    int cnt = 2 * emain; if (cnt > 8192) cnt = 8192;
    for (int i = 1 + 2 * threadIdx.x; i < cnt; i += 2 * blockDim.x)
        if (p[i] != 0u) bad = 1;
    __syncthreads();
    if (threadIdx.x == 0) g_is64 = bad ? 0 : 1;
}

// Fused: decode edges (+self loops) AND zero all accumulators.
__global__ __launch_bounds__(256) void k_prep(const void* __restrict__ ei,
                                              int emain, int n) {
    int etot = emain + n;
    int stride = gridDim.x * blockDim.x;
    int tid0 = blockIdx.x * blockDim.x + threadIdx.x;
    int is64 = g_is64;
    for (int e = tid0; e < etot; e += stride) {
        int s, d;
        if (e >= emain) { s = d = e - emain; }
        else if (is64) {
            const long long* p = (const long long*)ei;
            s = (int)p[e]; d = (int)p[emain + e];
        } else {
            const int* p = (const int*)ei;
            s = p[e]; d = p[emain + e];
        }
        g_edges[e] = make_int2(s, d);
    }
    for (int j = tid0; j < n; j += stride) g_s1[j] = 0.0f;
    for (int j = tid0; j < 2 * n; j += stride) g_s23[j] = 0.0f;
    int n32 = n * 32;
    for (int j = tid0; j < n32; j += stride) {
        g_agg1[j] = 0.0f; g_agg23[j] = 0.0f;
    }
}

// hlin1 = x @ W1 ; attention dots. 64 nodes/block, 2 nodes/thread.
__global__ __launch_bounds__(256) void k_gemm1(
    const float* __restrict__ x, const float* __restrict__ W1,
    const float* __restrict__ a1s, const float* __restrict__ a1d, int n)
{
    __shared__ float4 Ws4[128 * 8];    // [k][q] = W1[k][4q..4q+3]
    __shared__ float4 xs4[64 * 33];    // 64 nodes x (32 float4 + 1 pad)
    __shared__ float4 as4[8], ad4[8];
    int tid = threadIdx.x;
    const float4* W4 = (const float4*)W1;
    for (int i = tid; i < 1024; i += 256) Ws4[i] = W4[i];
    if (tid < 8)        as4[tid]     = ((const float4*)a1s)[tid];
    else if (tid < 16)  ad4[tid - 8] = ((const float4*)a1d)[tid - 8];

    int base = blockIdx.x * 64;
    const float4* xg = (const float4*)x + (size_t)base * 32;
    int navail = n - base; if (navail > 64) navail = 64;
    for (int f = tid; f < navail * 32; f += 256) {
        int node = f >> 5, j = f & 31;
        xs4[node * 33 + j] = xg[f];
    }
    __syncthreads();

    int warp = tid >> 5, lane = tid & 31;
    int pair = lane >> 3, q = lane & 7;
    int nodeL0 = warp * 8 + pair * 2;          // two nodes per thread
    int nodeL1 = nodeL0 + 1;
    int node0 = base + nodeL0, node1 = base + nodeL1;

    const float4* xr0 = xs4 + nodeL0 * 33;
    const float4* xr1 = xs4 + nodeL1 * 33;
    float4 acc0 = make_float4(0.f, 0.f, 0.f, 0.f);
    float4 acc1 = make_float4(0.f, 0.f, 0.f, 0.f);
    #pragma unroll 2
    for (int k4 = 0; k4 < 32; k4++) {
        float4 xv0 = xr0[k4];
        float4 xv1 = xr1[k4];
        float4 w0 = Ws4[(k4 * 4 + 0) * 8 + q];
        float4 w1 = Ws4[(k4 * 4 + 1) * 8 + q];
        float4 w2 = Ws4[(k4 * 4 + 2) * 8 + q];
        float4 w3 = Ws4[(k4 * 4 + 3) * 8 + q];
        fma4(acc0, xv0.x, w0); fma4(acc1, xv1.x, w0);
        fma4(acc0, xv0.y, w1); fma4(acc1, xv1.y, w1);
        fma4(acc0, xv0.z, w2); fma4(acc1, xv1.z, w2);
        fma4(acc0, xv0.w, w3); fma4(acc1, xv1.w, w3);
    }

    float4 av = as4[q], dv = ad4[q];
    float ts0 = acc0.x * av.x + acc0.y * av.y + acc0.z * av.z + acc0.w * av.w;
    float td0 = acc0.x * dv.x + acc0.y * dv.y + acc0.z * dv.z + acc0.w * dv.w;
    float ts1 = acc1.x * av.x + acc1.y * av.y + acc1.z * av.z + acc1.w * av.w;
    float td1 = acc1.x * dv.x + acc1.y * dv.y + acc1.z * dv.z + acc1.w * dv.w;
    #pragma unroll
    for (int off = 4; off >= 1; off >>= 1) {
        ts0 += __shfl_xor_sync(0xffffffffu, ts0, off);
        td0 += __shfl_xor_sync(0xffffffffu, td0, off);
        ts1 += __shfl_xor_sync(0xffffffffu, ts1, off);
        td1 += __shfl_xor_sync(0xffffffffu, td1, off);
    }
    if (node0 < n) {
        ((float4*)(g_hlin1 + (size_t)node0 * 32))[q] = acc0;
        if (q == 0) { g_as1[node0] = ts0; g_ad1[node0] = td0; }
    }
    if (node1 < n) {
        ((float4*)(g_hlin1 + (size_t)node1 * 32))[q] = acc1;
        if (q == 0) { g_as1[node1] = ts1; g_ad1[node1] = td1; }
    }
}

// Layer-1 edge pass A.
__global__ __launch_bounds__(256) void k_edgeA1(int etot)
{
    int stride = gridDim.x * blockDim.x;
    for (int e = blockIdx.x * blockDim.x + threadIdx.x; e < etot; e += stride) {
        int2 ed = g_edges[e];
        float v = g_as1[ed.x] + g_ad1[ed.y];
        v = (v > 0.0f) ? v : NEG_SLOPE * v;
        float ex = __expf(v);
        g_ex1[e] = ex;
        atomicAdd(&g_s1[ed.y], ex);
    }
}

__global__ void k_recip1(int n) {
    int i = blockIdx.x * blockDim.x + threadIdx.x;
    if (i < n) g_s1[i] = __frcp_rn(g_s1[i]);
}

// Layer-1 edge pass B: 8 lanes/edge, one float4 vector RED per lane.
__global__ __launch_bounds__(256) void k_edgeB1(int etot)
{
    int t = blockIdx.x * blockDim.x + threadIdx.x;
    int e = t >> 3;
    if (e >= etot) return;
    int q = t & 7;
    int2 ed = g_edges[e];
    float alpha = g_ex1[e] * g_s1[ed.y];
    const float4* hp = (const float4*)(g_hlin1 + (size_t)ed.x * 32);
    float4 h = hp[q];
    float4 v = make_float4(h.x * alpha, h.y * alpha, h.z * alpha, h.w * alpha);
    float* dp = g_agg1 + (size_t)ed.y * 32 + q * 4;
    asm volatile("red.global.add.v4.f32 [%0], {%1,%2,%3,%4};"
                 :: "l"(dp), "f"(v.x), "f"(v.y), "f"(v.z), "f"(v.w) : "memory");
}

// h1 = relu(agg1+b1); h23 = h1 @ [Wmu|Wls]; attn dots.
__global__ __launch_bounds__(256) void k_node2(
    const float* __restrict__ b1,
    const float* __restrict__ Wmu, const float* __restrict__ amus,
    const float* __restrict__ amud,
    const float* __restrict__ Wls, const float* __restrict__ alss,
    const float* __restrict__ alsd, int n)
{
    __shared__ float Wcat[32 * 32];
    __shared__ float4 h1s4[32 * 9];
    __shared__ float4 b1s4[8];
    __shared__ float4 srcv4[8], dstv4[8];
    int tid = threadIdx.x;
    for (int i = tid; i < 1024; i += 256) {
        int k = i >> 5, c = i & 31;
        Wcat[i] = (c < 16) ? Wmu[k * 16 + c] : Wls[k * 16 + (c - 16)];
    }
    if (tid < 8) b1s4[tid] = ((const float4*)b1)[tid];
    if (tid < 32) {
        float sv = (tid < 16) ? amus[tid] : alss[tid - 16];
        float dv = (tid < 16) ? amud[tid] : alsd[tid - 16];
        ((float*)srcv4)[tid] = sv;
        ((float*)dstv4)[tid] = dv;
    }
    __syncthreads();

    int warp = tid >> 5, lane = tid & 31;
    int nsub = lane >> 3, q = lane & 7;
    int nodeL = warp * 4 + nsub;
    int node = blockIdx.x * 32 + nodeL;
    if (node >= n) return;

    float4 a = ((const float4*)(g_agg1 + (size_t)node * 32))[q];
    float4 bb = b1s4[q];
    float4 h;
    h.x = fmaxf(a.x + bb.x, 0.f); h.y = fmaxf(a.y + bb.y, 0.f);
    h.z = fmaxf(a.z + bb.z, 0.f); h.w = fmaxf(a.w + bb.w, 0.f);
    h1s4[nodeL * 9 + q] = h;
    __syncwarp();

    const float4* hr = h1s4 + nodeL * 9;
    const float4* Wc4 = (const float4*)Wcat;
    float4 acc = make_float4(0.f, 0.f, 0.f, 0.f);
    #pragma unroll
    for (int k4 = 0; k4 < 8; k4++) {
        float4 hv = hr[k4];
        float4 w0 = Wc4[(k4 * 4 + 0) * 8 + q];
        float4 w1 = Wc4[(k4 * 4 + 1) * 8 + q];
        float4 w2 = Wc4[(k4 * 4 + 2) * 8 + q];
        float4 w3 = Wc4[(k4 * 4 + 3) * 8 + q];
        fma4(acc, hv.x, w0); fma4(acc, hv.y, w1);
        fma4(acc, hv.z, w2); fma4(acc, hv.w, w3);
    }
    ((float4*)(g_h23 + (size_t)node * 32))[q] = acc;

    float4 av = srcv4[q], dv = dstv4[q];
    float ts = acc.x * av.x + acc.y * av.y + acc.z * av.z + acc.w * av.w;
    float td = acc.x * dv.x + acc.y * dv.y + acc.z * dv.z + acc.w * dv.w;
    #pragma unroll
    for (int off = 2; off >= 1; off >>= 1) {
        ts += __shfl_xor_sync(0xffffffffu, ts, off);
        td += __shfl_xor_sync(0xffffffffu, td, off);
    }
    if (q == 0) { g_src23[2 * node + 0] = ts; g_dst23[2 * node + 0] = td; }
    if (q == 4) { g_src23[2 * node + 1] = ts; g_dst23[2 * node + 1] = td; }
}

// Fused mu+logstd edge pass A.
__global__ __launch_bounds__(256) void k_edgeA23(int etot)
{
    int stride = gridDim.x * blockDim.x;
    for (int e = blockIdx.x * blockDim.x + threadIdx.x; e < etot; e += stride) {
        int2 ed = g_edges[e];
        float2 sv = *(const float2*)(g_src23 + 2 * ed.x);
        float2 dv = *(const float2*)(g_dst23 + 2 * ed.y);
        float vmu = sv.x + dv.x;
        float vls = sv.y + dv.y;
        vmu = (vmu > 0.0f) ? vmu : NEG_SLOPE * vmu;
        vls = (vls > 0.0f) ? vls : NEG_SLOPE * vls;
        float exmu = __expf(vmu);
        float exls = __expf(vls);
        *(float2*)(g_ex23 + 2 * e) = make_float2(exmu, exls);
        float* dp = g_s23 + 2 * ed.y;
        asm volatile("red.global.add.v2.f32 [%0], {%1,%2};"
                     :: "l"(dp), "f"(exmu), "f"(exls) : "memory");
    }
}

__global__ void k_recip23(int n) {
    int i = blockIdx.x * blockDim.x + threadIdx.x;
    if (i < 2 * n) g_s23[i] = __frcp_rn(g_s23[i]);
}

// Fused mu+logstd edge pass B.
__global__ __launch_bounds__(256) void k_edgeB23(int etot)
{
    int t = blockIdx.x * blockDim.x + threadIdx.x;
    int e = t >> 3;
    if (e >= etot) return;
    int q = t & 7;
    int2 ed = g_edges[e];
    float2 ex  = *(const float2*)(g_ex23 + 2 * e);
    float2 inv = *(const float2*)(g_s23  + 2 * ed.y);
    float alpha = (q < 4) ? ex.x * inv.x : ex.y * inv.y;
    const float4* hp = (const float4*)(g_h23 + (size_t)ed.x * 32);
    float4 h = hp[q];
    float4 v = make_float4(h.x * alpha, h.y * alpha, h.z * alpha, h.w * alpha);
    float* dp = g_agg23 + (size_t)ed.y * 32 + q * 4;
    asm volatile("red.global.add.v4.f32 [%0], {%1,%2,%3,%4};"
                 :: "l"(dp), "f"(v.x), "f"(v.y), "f"(v.z), "f"(v.w) : "memory");
}

// Split interleaved agg into (mu | logstd) halves of d_out, add biases.
__global__ __launch_bounds__(256) void k_final(
    const float* __restrict__ bmu, const float* __restrict__ bls,
    float* __restrict__ out, int n)
{
    int total = n * 16;
    int stride = gridDim.x * blockDim.x;
    for (int i = blockIdx.x * blockDim.x + threadIdx.x; i < total; i += stride) {
        int node = i >> 4, c = i & 15;
        out[i]         = g_agg23[node * 32 + c]      + bmu[c];
        out[total + i] = g_agg23[node * 32 + 16 + c] + bls[c];
    }
}

// ---------------- launch ---------------------------------------------
extern "C" void kernel_launch(void* const* d_in, const int* in_sizes, int n_in,
                              void* d_out, int out_size)
{
    const float* x    = (const float*)d_in[0];
    const void*  ei   = d_in[1];
    const float* W1   = (const float*)d_in[2];
    const float* a1s  = (const float*)d_in[3];
    const float* a1d  = (const float*)d_in[4];
    const float* b1   = (const float*)d_in[5];
    const float* Wmu  = (const float*)d_in[6];
    const float* amus = (const float*)d_in[7];
    const float* amud = (const float*)d_in[8];
    const float* bmu  = (const float*)d_in[9];
    const float* Wls  = (const float*)d_in[10];
    const float* alss = (const float*)d_in[11];
    const float* alsd = (const float*)d_in[12];
    const float* bls  = (const float*)d_in[13];

    int n     = in_sizes[0] / 128;      // 100000
    int emain = in_sizes[1] / 2;        // 1600000
    int etot  = emain + n;
    float* out = (float*)d_out;

    k_detect<<<1, 256>>>((const unsigned int*)ei, emain);
    k_prep<<<2048, 256>>>(ei, emain, n);
    k_gemm1<<<(n + 63) / 64, 256>>>(x, W1, a1s, a1d, n);
    k_edgeA1<<<(etot + 255) / 256, 256>>>(etot);
    k_recip1<<<(n + 255) / 256, 256>>>(n);
    k_edgeB1<<<(etot * 8 + 255) / 256, 256>>>(etot);
    k_node2<<<(n + 31) / 32, 256>>>(b1, Wmu, amus, amud, Wls, alss, alsd, n);
    k_edgeA23<<<(etot + 255) / 256, 256>>>(etot);
    k_recip23<<<(2 * n + 255) / 256, 256>>>(n);
    k_edgeB23<<<(etot * 8 + 255) / 256, 256>>>(etot);
    k_final<<<2048, 256>>>(bmu, bls, out, n);
}

// round 6
// speedup vs baseline: 3.4802x; 1.0697x over previous
#include <cuda_runtime.h>

// ---------------- problem constants (from reference) ----------------
#define NMAX   100000
#define EMAX   1700032
#define NEG_SLOPE 0.2f

__device__ __forceinline__ void fma4(float4& acc, float s, const float4& wv) {
    acc.x = fmaf(s, wv.x, acc.x); acc.y = fmaf(s, wv.y, acc.y);
    acc.z = fmaf(s, wv.z, acc.z); acc.w = fmaf(s, wv.w, acc.w);
}

// ---------------- scratch (device globals; no allocation allowed) ---
__device__ __align__(16) float g_hlin1[NMAX * 32];
__device__ float g_as1[NMAX];
__device__ float g_ad1[NMAX];
__device__ float g_s1[NMAX];                         // softmax denominator L1
__device__ __align__(16) float g_agg1[NMAX * 32];    // UNNORMALIZED sum ex*h

__device__ __align__(16) float g_h23[NMAX * 32];     // interleaved mu|ls
__device__ __align__(8)  float g_src23[NMAX * 2];
__device__ __align__(8)  float g_dst23[NMAX * 2];
__device__ __align__(8)  float g_s23[NMAX * 2];      // {smu, sls} denominators
__device__ __align__(16) float g_agg23[NMAX * 32];   // UNNORMALIZED

__device__ __align__(8)  int2  g_edges[EMAX];
__device__ int   g_is64;

// ---------------- kernels -------------------------------------------

__global__ void k_detect(const unsigned int* __restrict__ p, int emain) {
    __shared__ int bad;
    if (threadIdx.x == 0) bad = 0;
    __syncthreads();
    int cnt = 2 * emain; if (cnt > 8192) cnt = 8192;
    for (int i = 1 + 2 * threadIdx.x; i < cnt; i += 2 * blockDim.x)
        if (p[i] != 0u) bad = 1;
    __syncthreads();
    if (threadIdx.x == 0) g_is64 = bad ? 0 : 1;
}

// Fused: decode edges (+self loops) AND zero all accumulators.
__global__ __launch_bounds__(256) void k_prep(const void* __restrict__ ei,
                                              int emain, int n) {
    int etot = emain + n;
    int stride = gridDim.x * blockDim.x;
    int tid0 = blockIdx.x * blockDim.x + threadIdx.x;
    int is64 = g_is64;
    for (int e = tid0; e < etot; e += stride) {
        int s, d;
        if (e >= emain) { s = d = e - emain; }
        else if (is64) {
            const long long* p = (const long long*)ei;
            s = (int)p[e]; d = (int)p[emain + e];
        } else {
            const int* p = (const int*)ei;
            s = p[e]; d = p[emain + e];
        }
        g_edges[e] = make_int2(s, d);
    }
    for (int j = tid0; j < n; j += stride) g_s1[j] = 0.0f;
    for (int j = tid0; j < 2 * n; j += stride) g_s23[j] = 0.0f;
    int n32 = n * 32;
    for (int j = tid0; j < n32; j += stride) {
        g_agg1[j] = 0.0f; g_agg23[j] = 0.0f;
    }
}

// hlin1 = x @ W1 ; attention dots. 64 nodes/block, 2 nodes/thread.
__global__ __launch_bounds__(256) void k_gemm1(
    const float* __restrict__ x, const float* __restrict__ W1,
    const float* __restrict__ a1s, const float* __restrict__ a1d, int n)
{
    __shared__ float4 Ws4[128 * 8];
    __shared__ float4 xs4[64 * 33];
    __shared__ float4 as4[8], ad4[8];
    int tid = threadIdx.x;
    const float4* W4 = (const float4*)W1;
    for (int i = tid; i < 1024; i += 256) Ws4[i] = W4[i];
    if (tid < 8)        as4[tid]     = ((const float4*)a1s)[tid];
    else if (tid < 16)  ad4[tid - 8] = ((const float4*)a1d)[tid - 8];

    int base = blockIdx.x * 64;
    const float4* xg = (const float4*)x + (size_t)base * 32;
    int navail = n - base; if (navail > 64) navail = 64;
    for (int f = tid; f < navail * 32; f += 256) {
        int node = f >> 5, j = f & 31;
        xs4[node * 33 + j] = xg[f];
    }
    __syncthreads();

    int warp = tid >> 5, lane = tid & 31;
    int pair = lane >> 3, q = lane & 7;
    int nodeL0 = warp * 8 + pair * 2;
    int nodeL1 = nodeL0 + 1;
    int node0 = base + nodeL0, node1 = base + nodeL1;

    const float4* xr0 = xs4 + nodeL0 * 33;
    const float4* xr1 = xs4 + nodeL1 * 33;
    float4 acc0 = make_float4(0.f, 0.f, 0.f, 0.f);
    float4 acc1 = make_float4(0.f, 0.f, 0.f, 0.f);
    #pragma unroll 2
    for (int k4 = 0; k4 < 32; k4++) {
        float4 xv0 = xr0[k4];
        float4 xv1 = xr1[k4];
        float4 w0 = Ws4[(k4 * 4 + 0) * 8 + q];
        float4 w1 = Ws4[(k4 * 4 + 1) * 8 + q];
        float4 w2 = Ws4[(k4 * 4 + 2) * 8 + q];
        float4 w3 = Ws4[(k4 * 4 + 3) * 8 + q];
        fma4(acc0, xv0.x, w0); fma4(acc1, xv1.x, w0);
        fma4(acc0, xv0.y, w1); fma4(acc1, xv1.y, w1);
        fma4(acc0, xv0.z, w2); fma4(acc1, xv1.z, w2);
        fma4(acc0, xv0.w, w3); fma4(acc1, xv1.w, w3);
    }

    float4 av = as4[q], dv = ad4[q];
    float ts0 = acc0.x * av.x + acc0.y * av.y + acc0.z * av.z + acc0.w * av.w;
    float td0 = acc0.x * dv.x + acc0.y * dv.y + acc0.z * dv.z + acc0.w * dv.w;
    float ts1 = acc1.x * av.x + acc1.y * av.y + acc1.z * av.z + acc1.w * av.w;
    float td1 = acc1.x * dv.x + acc1.y * dv.y + acc1.z * dv.z + acc1.w * dv.w;
    #pragma unroll
    for (int off = 4; off >= 1; off >>= 1) {
        ts0 += __shfl_xor_sync(0xffffffffu, ts0, off);
        td0 += __shfl_xor_sync(0xffffffffu, td0, off);
        ts1 += __shfl_xor_sync(0xffffffffu, ts1, off);
        td1 += __shfl_xor_sync(0xffffffffu, td1, off);
    }
    if (node0 < n) {
        ((float4*)(g_hlin1 + (size_t)node0 * 32))[q] = acc0;
        if (q == 0) { g_as1[node0] = ts0; g_ad1[node0] = td0; }
    }
    if (node1 < n) {
        ((float4*)(g_hlin1 + (size_t)node1 * 32))[q] = acc1;
        if (q == 0) { g_as1[node1] = ts1; g_ad1[node1] = td1; }
    }
}

// Fused layer-1 edge pass: agg1 += ex*h, s1 += ex. 8 lanes/edge.
__global__ __launch_bounds__(256) void k_edge1(int etot)
{
    int t = blockIdx.x * blockDim.x + threadIdx.x;
    int e = t >> 3;
    bool act = (e < etot);
    if (!act) e = etot - 1;            // clamp: keep shfl masks full
    int lane = threadIdx.x & 31;
    int q = lane & 7;
    int2 ed = g_edges[e];
    float v = 0.0f;
    if (q == 0) v = g_as1[ed.x] + g_ad1[ed.y];
    v = __shfl_sync(0xffffffffu, v, lane & 24);   // group-leader broadcast
    v = (v > 0.0f) ? v : NEG_SLOPE * v;
    float ex = __expf(v);
    float4 h = ((const float4*)(g_hlin1 + (size_t)ed.x * 32))[q];
    if (act) {
        float4 w = make_float4(h.x * ex, h.y * ex, h.z * ex, h.w * ex);
        float* dp = g_agg1 + (size_t)ed.y * 32 + q * 4;
        asm volatile("red.global.add.v4.f32 [%0], {%1,%2,%3,%4};"
                     :: "l"(dp), "f"(w.x), "f"(w.y), "f"(w.z), "f"(w.w) : "memory");
        if (q == 0)
            asm volatile("red.global.add.f32 [%0], %1;"
                         :: "l"(g_s1 + ed.y), "f"(ex) : "memory");
    }
}

// h1 = relu(agg1/s1 + b1); h23 = h1 @ [Wmu|Wls]; attn dots.
__global__ __launch_bounds__(256) void k_node2(
    const float* __restrict__ b1,
    const float* __restrict__ Wmu, const float* __restrict__ amus,
    const float* __restrict__ amud,
    const float* __restrict__ Wls, const float* __restrict__ alss,
    const float* __restrict__ alsd, int n)
{
    __shared__ float Wcat[32 * 32];
    __shared__ float4 h1s4[32 * 9];
    __shared__ float4 b1s4[8];
    __shared__ float4 srcv4[8], dstv4[8];
    int tid = threadIdx.x;
    for (int i = tid; i < 1024; i += 256) {
        int k = i >> 5, c = i & 31;
        Wcat[i] = (c < 16) ? Wmu[k * 16 + c] : Wls[k * 16 + (c - 16)];
    }
    if (tid < 8) b1s4[tid] = ((const float4*)b1)[tid];
    if (tid < 32) {
        float sv = (tid < 16) ? amus[tid] : alss[tid - 16];
        float dv = (tid < 16) ? amud[tid] : alsd[tid - 16];
        ((float*)srcv4)[tid] = sv;
        ((float*)dstv4)[tid] = dv;
    }
    __syncthreads();

    int warp = tid >> 5, lane = tid & 31;
    int nsub = lane >> 3, q = lane & 7;
    int nodeL = warp * 4 + nsub;
    int node = blockIdx.x * 32 + nodeL;
    if (node >= n) return;

    float inv = __frcp_rn(g_s1[node]);
    float4 a = ((const float4*)(g_agg1 + (size_t)node * 32))[q];
    float4 bb = b1s4[q];
    float4 h;
    h.x = fmaxf(fmaf(a.x, inv, bb.x), 0.f);
    h.y = fmaxf(fmaf(a.y, inv, bb.y), 0.f);
    h.z = fmaxf(fmaf(a.z, inv, bb.z), 0.f);
    h.w = fmaxf(fmaf(a.w, inv, bb.w), 0.f);
    h1s4[nodeL * 9 + q] = h;
    __syncwarp();

    const float4* hr = h1s4 + nodeL * 9;
    const float4* Wc4 = (const float4*)Wcat;
    float4 acc = make_float4(0.f, 0.f, 0.f, 0.f);
    #pragma unroll
    for (int k4 = 0; k4 < 8; k4++) {
        float4 hv = hr[k4];
        float4 w0 = Wc4[(k4 * 4 + 0) * 8 + q];
        float4 w1 = Wc4[(k4 * 4 + 1) * 8 + q];
        float4 w2 = Wc4[(k4 * 4 + 2) * 8 + q];
        float4 w3 = Wc4[(k4 * 4 + 3) * 8 + q];
        fma4(acc, hv.x, w0); fma4(acc, hv.y, w1);
        fma4(acc, hv.z, w2); fma4(acc, hv.w, w3);
    }
    ((float4*)(g_h23 + (size_t)node * 32))[q] = acc;

    float4 av = srcv4[q], dv = dstv4[q];
    float ts = acc.x * av.x + acc.y * av.y + acc.z * av.z + acc.w * av.w;
    float td = acc.x * dv.x + acc.y * dv.y + acc.z * dv.z + acc.w * dv.w;
    #pragma unroll
    for (int off = 2; off >= 1; off >>= 1) {
        ts += __shfl_xor_sync(0xffffffffu, ts, off);
        td += __shfl_xor_sync(0xffffffffu, td, off);
    }
    if (q == 0) { g_src23[2 * node + 0] = ts; g_dst23[2 * node + 0] = td; }
    if (q == 4) { g_src23[2 * node + 1] = ts; g_dst23[2 * node + 1] = td; }
}

// Fused mu+logstd edge pass: agg23 += ex*h23, s23 += {exmu,exls}.
__global__ __launch_bounds__(256) void k_edge23(int etot)
{
    int t = blockIdx.x * blockDim.x + threadIdx.x;
    int e = t >> 3;
    bool act = (e < etot);
    if (!act) e = etot - 1;
    int lane = threadIdx.x & 31;
    int q = lane & 7;
    int2 ed = g_edges[e];
    float vmu = 0.0f, vls = 0.0f;
    if (q == 0) {
        float2 sv = *(const float2*)(g_src23 + 2 * ed.x);
        float2 dv = *(const float2*)(g_dst23 + 2 * ed.y);
        vmu = sv.x + dv.x;
        vls = sv.y + dv.y;
    }
    int src_lane = lane & 24;
    vmu = __shfl_sync(0xffffffffu, vmu, src_lane);
    vls = __shfl_sync(0xffffffffu, vls, src_lane);
    vmu = (vmu > 0.0f) ? vmu : NEG_SLOPE * vmu;
    vls = (vls > 0.0f) ? vls : NEG_SLOPE * vls;
    float exmu = __expf(vmu);
    float exls = __expf(vls);
    float ex = (q < 4) ? exmu : exls;
    float4 h = ((const float4*)(g_h23 + (size_t)ed.x * 32))[q];
    if (act) {
        float4 w = make_float4(h.x * ex, h.y * ex, h.z * ex, h.w * ex);
        float* dp = g_agg23 + (size_t)ed.y * 32 + q * 4;
        asm volatile("red.global.add.v4.f32 [%0], {%1,%2,%3,%4};"
                     :: "l"(dp), "f"(w.x), "f"(w.y), "f"(w.z), "f"(w.w) : "memory");
        if (q == 0)
            asm volatile("red.global.add.v2.f32 [%0], {%1,%2};"
                         :: "l"(g_s23 + 2 * ed.y), "f"(exmu), "f"(exls) : "memory");
    }
}

// out = agg23/s + bias, de-interleave mu | logstd.
__global__ __launch_bounds__(256) void k_final(
    const float* __restrict__ bmu, const float* __restrict__ bls,
    float* __restrict__ out, int n)
{
    int total = n * 16;
    int stride = gridDim.x * blockDim.x;
    for (int i = blockIdx.x * blockDim.x + threadIdx.x; i < total; i += stride) {
        int node = i >> 4, c = i & 15;
        float2 s = *(const float2*)(g_s23 + 2 * node);
        out[i]         = g_agg23[node * 32 + c]      * __frcp_rn(s.x) + bmu[c];
        out[total + i] = g_agg23[node * 32 + 16 + c] * __frcp_rn(s.y) + bls[c];
    }
}

// ---------------- launch ---------------------------------------------
extern "C" void kernel_launch(void* const* d_in, const int* in_sizes, int n_in,
                              void* d_out, int out_size)
{
    const float* x    = (const float*)d_in[0];
    const void*  ei   = d_in[1];
    const float* W1   = (const float*)d_in[2];
    const float* a1s  = (const float*)d_in[3];
    const float* a1d  = (const float*)d_in[4];
    const float* b1   = (const float*)d_in[5];
    const float* Wmu  = (const float*)d_in[6];
    const float* amus = (const float*)d_in[7];
    const float* amud = (const float*)d_in[8];
    const float* bmu  = (const float*)d_in[9];
    const float* Wls  = (const float*)d_in[10];
    const float* alss = (const float*)d_in[11];
    const float* alsd = (const float*)d_in[12];
    const float* bls  = (const float*)d_in[13];

    int n     = in_sizes[0] / 128;      // 100000
    int emain = in_sizes[1] / 2;        // 1600000
    int etot  = emain + n;
    float* out = (float*)d_out;

    k_detect<<<1, 256>>>((const unsigned int*)ei, emain);
    k_prep<<<2048, 256>>>(ei, emain, n);
    k_gemm1<<<(n + 63) / 64, 256>>>(x, W1, a1s, a1d, n);
    k_edge1<<<(etot * 8 + 255) / 256, 256>>>(etot);
    k_node2<<<(n + 31) / 32, 256>>>(b1, Wmu, amus, amud, Wls, alss, alsd, n);
    k_edge23<<<(etot * 8 + 255) / 256, 256>>>(etot);
    k_final<<<2048, 256>>>(bmu, bls, out, n);
}

// round 7
// speedup vs baseline: 4.2850x; 1.2312x over previous
#include <cuda_runtime.h>

// ---------------- problem constants (from reference) ----------------
#define NMAX   100000
#define EMAX   1700032
#define NEG_SLOPE 0.2f

__device__ __forceinline__ void fma4(float4& acc, float s, const float4& wv) {
    acc.x = fmaf(s, wv.x, acc.x); acc.y = fmaf(s, wv.y, acc.y);
    acc.z = fmaf(s, wv.z, acc.z); acc.w = fmaf(s, wv.w, acc.w);
}
__device__ __forceinline__ float lrelu(float v) {
    return (v > 0.0f) ? v : NEG_SLOPE * v;
}

// ---------------- scratch (device globals) --------------------------
__device__ __align__(16) float g_hlin1[NMAX * 32];   // x@W1 (pre-bias)
__device__ float g_as1[NMAX];
__device__ float g_ad1[NMAX];
__device__ __align__(16) float g_h1[NMAX * 32];      // relu(norm-agg + b1)

__device__ __align__(16) float g_h23[NMAX * 32];     // interleaved mu|ls
__device__ __align__(8)  float g_src23[NMAX * 2];
__device__ __align__(8)  float g_dst23[NMAX * 2];

__device__ __align__(8)  int2  g_edges[EMAX];
__device__ int   g_deg[NMAX];
__device__ int   g_off[NMAX + 1];
__device__ int   g_cur[NMAX];
__device__ int   g_bsum[128];
__device__ int   g_csr[EMAX];        // src ids grouped by dst
__device__ int   g_is64;

// ---------------- CSR build -----------------------------------------

__global__ void k_detect(const unsigned int* __restrict__ p, int emain) {
    __shared__ int bad;
    if (threadIdx.x == 0) bad = 0;
    __syncthreads();
    int cnt = 2 * emain; if (cnt > 8192) cnt = 8192;
    for (int i = 1 + 2 * threadIdx.x; i < cnt; i += 2 * blockDim.x)
        if (p[i] != 0u) bad = 1;
    __syncthreads();
    if (threadIdx.x == 0) g_is64 = bad ? 0 : 1;
}

// decode edges (+ self loops) and zero degree counters
__global__ __launch_bounds__(256) void k_prep(const void* __restrict__ ei,
                                              int emain, int n) {
    int etot = emain + n;
    int stride = gridDim.x * blockDim.x;
    int tid0 = blockIdx.x * blockDim.x + threadIdx.x;
    int is64 = g_is64;
    for (int e = tid0; e < etot; e += stride) {
        int s, d;
        if (e >= emain) { s = d = e - emain; }
        else if (is64) {
            const long long* p = (const long long*)ei;
            s = (int)p[e]; d = (int)p[emain + e];
        } else {
            const int* p = (const int*)ei;
            s = p[e]; d = p[emain + e];
        }
        g_edges[e] = make_int2(s, d);
    }
    for (int j = tid0; j < n; j += stride) g_deg[j] = 0;
}

__global__ __launch_bounds__(256) void k_hist(int etot) {
    int stride = gridDim.x * blockDim.x;
    for (int e = blockIdx.x * blockDim.x + threadIdx.x; e < etot; e += stride)
        atomicAdd(&g_deg[g_edges[e].y], 1);
}

// block-level exclusive scan: 1024 elems/block, 4/thread
__global__ __launch_bounds__(256) void k_scanA(int n) {
    __shared__ int ts[256];
    int b = blockIdx.x, tid = threadIdx.x;
    int base = b * 1024 + tid * 4;
    int v0 = (base + 0 < n) ? g_deg[base + 0] : 0;
    int v1 = (base + 1 < n) ? g_deg[base + 1] : 0;
    int v2 = (base + 2 < n) ? g_deg[base + 2] : 0;
    int v3 = (base + 3 < n) ? g_deg[base + 3] : 0;
    int tsum = v0 + v1 + v2 + v3;
    ts[tid] = tsum;
    __syncthreads();
    #pragma unroll
    for (int d = 1; d < 256; d <<= 1) {
        int t = (tid >= d) ? ts[tid - d] : 0;
        __syncthreads();
        ts[tid] += t;
        __syncthreads();
    }
    int excl = (tid > 0) ? ts[tid - 1] : 0;
    int run = excl;
    if (base + 0 < n) { g_off[base + 0] = run; } run += v0;
    if (base + 1 < n) { g_off[base + 1] = run; } run += v1;
    if (base + 2 < n) { g_off[base + 2] = run; } run += v2;
    if (base + 3 < n) { g_off[base + 3] = run; } run += v3;
    if (tid == 255) g_bsum[b] = ts[255];
}

__global__ void k_scanB(int nblk) {
    __shared__ int s[128];
    int tid = threadIdx.x;
    s[tid] = (tid < nblk) ? g_bsum[tid] : 0;
    __syncthreads();
    #pragma unroll
    for (int d = 1; d < 128; d <<= 1) {
        int t = (tid >= d) ? s[tid - d] : 0;
        __syncthreads();
        s[tid] += t;
        __syncthreads();
    }
    if (tid < nblk) g_bsum[tid] = (tid > 0) ? s[tid - 1] : 0;
}

__global__ __launch_bounds__(256) void k_scanC(int n, int etot) {
    int b = blockIdx.x, tid = threadIdx.x;
    int add = g_bsum[b];
    int base = b * 1024 + tid * 4;
    #pragma unroll
    for (int j = 0; j < 4; j++) {
        int i = base + j;
        if (i < n) {
            int v = g_off[i] + add;
            g_off[i] = v;
            g_cur[i] = v;
        }
    }
    if (b == 0 && tid == 0) g_off[n] = etot;
}

__global__ __launch_bounds__(256) void k_scatter(int etot) {
    int stride = gridDim.x * blockDim.x;
    for (int e = blockIdx.x * blockDim.x + threadIdx.x; e < etot; e += stride) {
        int2 ed = g_edges[e];
        int pos = atomicAdd(&g_cur[ed.y], 1);
        g_csr[pos] = ed.x;
    }
}

// ---------------- compute kernels -----------------------------------

// hlin1 = x @ W1 ; attention dots. 64 nodes/block, 2 nodes/thread.
__global__ __launch_bounds__(256) void k_gemm1(
    const float* __restrict__ x, const float* __restrict__ W1,
    const float* __restrict__ a1s, const float* __restrict__ a1d, int n)
{
    __shared__ float4 Ws4[128 * 8];
    __shared__ float4 xs4[64 * 33];
    __shared__ float4 as4[8], ad4[8];
    int tid = threadIdx.x;
    const float4* W4 = (const float4*)W1;
    for (int i = tid; i < 1024; i += 256) Ws4[i] = W4[i];
    if (tid < 8)        as4[tid]     = ((const float4*)a1s)[tid];
    else if (tid < 16)  ad4[tid - 8] = ((const float4*)a1d)[tid - 8];

    int base = blockIdx.x * 64;
    const float4* xg = (const float4*)x + (size_t)base * 32;
    int navail = n - base; if (navail > 64) navail = 64;
    for (int f = tid; f < navail * 32; f += 256) {
        int node = f >> 5, j = f & 31;
        xs4[node * 33 + j] = xg[f];
    }
    __syncthreads();

    int warp = tid >> 5, lane = tid & 31;
    int pair = lane >> 3, q = lane & 7;
    int nodeL0 = warp * 8 + pair * 2;
    int nodeL1 = nodeL0 + 1;
    int node0 = base + nodeL0, node1 = base + nodeL1;

    const float4* xr0 = xs4 + nodeL0 * 33;
    const float4* xr1 = xs4 + nodeL1 * 33;
    float4 acc0 = make_float4(0.f, 0.f, 0.f, 0.f);
    float4 acc1 = make_float4(0.f, 0.f, 0.f, 0.f);
    #pragma unroll 2
    for (int k4 = 0; k4 < 32; k4++) {
        float4 xv0 = xr0[k4];
        float4 xv1 = xr1[k4];
        float4 w0 = Ws4[(k4 * 4 + 0) * 8 + q];
        float4 w1 = Ws4[(k4 * 4 + 1) * 8 + q];
        float4 w2 = Ws4[(k4 * 4 + 2) * 8 + q];
        float4 w3 = Ws4[(k4 * 4 + 3) * 8 + q];
        fma4(acc0, xv0.x, w0); fma4(acc1, xv1.x, w0);
        fma4(acc0, xv0.y, w1); fma4(acc1, xv1.y, w1);
        fma4(acc0, xv0.z, w2); fma4(acc1, xv1.z, w2);
        fma4(acc0, xv0.w, w3); fma4(acc1, xv1.w, w3);
    }

    float4 av = as4[q], dv = ad4[q];
    float ts0 = acc0.x * av.x + acc0.y * av.y + acc0.z * av.z + acc0.w * av.w;
    float td0 = acc0.x * dv.x + acc0.y * dv.y + acc0.z * dv.z + acc0.w * dv.w;
    float ts1 = acc1.x * av.x + acc1.y * av.y + acc1.z * av.z + acc1.w * av.w;
    float td1 = acc1.x * dv.x + acc1.y * dv.y + acc1.z * dv.z + acc1.w * dv.w;
    #pragma unroll
    for (int off = 4; off >= 1; off >>= 1) {
        ts0 += __shfl_xor_sync(0xffffffffu, ts0, off);
        td0 += __shfl_xor_sync(0xffffffffu, td0, off);
        ts1 += __shfl_xor_sync(0xffffffffu, ts1, off);
        td1 += __shfl_xor_sync(0xffffffffu, td1, off);
    }
    if (node0 < n) {
        ((float4*)(g_hlin1 + (size_t)node0 * 32))[q] = acc0;
        if (q == 0) { g_as1[node0] = ts0; g_ad1[node0] = td0; }
    }
    if (node1 < n) {
        ((float4*)(g_hlin1 + (size_t)node1 * 32))[q] = acc1;
        if (q == 0) { g_as1[node1] = ts1; g_ad1[node1] = td1; }
    }
}

// Layer-1 gather: 8 lanes per dst node; no atomics; writes normalized
// h1 = relu(sum(ex*h)/sum(ex) + b1).
__global__ __launch_bounds__(256) void k_gather1(const float* __restrict__ b1,
                                                 int n)
{
    int t = blockIdx.x * blockDim.x + threadIdx.x;
    int node = t >> 3;
    if (node >= n) return;
    int q = t & 7;
    float ad = g_ad1[node];
    int off0 = g_off[node], off1 = g_off[node + 1];
    float4 acc = make_float4(0.f, 0.f, 0.f, 0.f);
    float s = 0.0f;
    #pragma unroll 4
    for (int i = off0; i < off1; i++) {
        int src = g_csr[i];
        float ex = __expf(lrelu(g_as1[src] + ad));
        float4 h = ((const float4*)(g_hlin1 + (size_t)src * 32))[q];
        fma4(acc, ex, h);
        s += ex;
    }
    float inv = __frcp_rn(s);
    float4 bb = ((const float4*)b1)[q];
    float4 o;
    o.x = fmaxf(fmaf(acc.x, inv, bb.x), 0.f);
    o.y = fmaxf(fmaf(acc.y, inv, bb.y), 0.f);
    o.z = fmaxf(fmaf(acc.z, inv, bb.z), 0.f);
    o.w = fmaxf(fmaf(acc.w, inv, bb.w), 0.f);
    ((float4*)(g_h1 + (size_t)node * 32))[q] = o;
}

// h23 = h1 @ [Wmu|Wls] interleaved; attention dots.
__global__ __launch_bounds__(256) void k_node2(
    const float* __restrict__ Wmu, const float* __restrict__ amus,
    const float* __restrict__ amud,
    const float* __restrict__ Wls, const float* __restrict__ alss,
    const float* __restrict__ alsd, int n)
{
    __shared__ float Wcat[32 * 32];
    __shared__ float4 h1s4[32 * 9];
    __shared__ float4 srcv4[8], dstv4[8];
    int tid = threadIdx.x;
    for (int i = tid; i < 1024; i += 256) {
        int k = i >> 5, c = i & 31;
        Wcat[i] = (c < 16) ? Wmu[k * 16 + c] : Wls[k * 16 + (c - 16)];
    }
    if (tid < 32) {
        float sv = (tid < 16) ? amus[tid] : alss[tid - 16];
        float dv = (tid < 16) ? amud[tid] : alsd[tid - 16];
        ((float*)srcv4)[tid] = sv;
        ((float*)dstv4)[tid] = dv;
    }
    __syncthreads();

    int warp = tid >> 5, lane = tid & 31;
    int nsub = lane >> 3, q = lane & 7;
    int nodeL = warp * 4 + nsub;
    int node = blockIdx.x * 32 + nodeL;
    if (node >= n) return;

    float4 h = ((const float4*)(g_h1 + (size_t)node * 32))[q];
    h1s4[nodeL * 9 + q] = h;
    __syncwarp();

    const float4* hr = h1s4 + nodeL * 9;
    const float4* Wc4 = (const float4*)Wcat;
    float4 acc = make_float4(0.f, 0.f, 0.f, 0.f);
    #pragma unroll
    for (int k4 = 0; k4 < 8; k4++) {
        float4 hv = hr[k4];
        float4 w0 = Wc4[(k4 * 4 + 0) * 8 + q];
        float4 w1 = Wc4[(k4 * 4 + 1) * 8 + q];
        float4 w2 = Wc4[(k4 * 4 + 2) * 8 + q];
        float4 w3 = Wc4[(k4 * 4 + 3) * 8 + q];
        fma4(acc, hv.x, w0); fma4(acc, hv.y, w1);
        fma4(acc, hv.z, w2); fma4(acc, hv.w, w3);
    }
    ((float4*)(g_h23 + (size_t)node * 32))[q] = acc;

    float4 av = srcv4[q], dv = dstv4[q];
    float ts = acc.x * av.x + acc.y * av.y + acc.z * av.z + acc.w * av.w;
    float td = acc.x * dv.x + acc.y * dv.y + acc.z * dv.z + acc.w * dv.w;
    #pragma unroll
    for (int off = 2; off >= 1; off >>= 1) {
        ts += __shfl_xor_sync(0xffffffffu, ts, off);
        td += __shfl_xor_sync(0xffffffffu, td, off);
    }
    if (q == 0) { g_src23[2 * node + 0] = ts; g_dst23[2 * node + 0] = td; }
    if (q == 4) { g_src23[2 * node + 1] = ts; g_dst23[2 * node + 1] = td; }
}

// Layer-2 gather (mu+ls fused): 8 lanes per dst node; writes final output.
__global__ __launch_bounds__(256) void k_gather23(
    const float* __restrict__ bmu, const float* __restrict__ bls,
    float* __restrict__ out, int n)
{
    int t = blockIdx.x * blockDim.x + threadIdx.x;
    int node = t >> 3;
    if (node >= n) return;
    int q = t & 7;
    float2 dv = *(const float2*)(g_dst23 + 2 * node);
    int off0 = g_off[node], off1 = g_off[node + 1];
    float4 acc = make_float4(0.f, 0.f, 0.f, 0.f);
    float smu = 0.0f, sls = 0.0f;
    bool is_mu = (q < 4);
    #pragma unroll 4
    for (int i = off0; i < off1; i++) {
        int src = g_csr[i];
        float2 sv = *(const float2*)(g_src23 + 2 * src);
        float exmu = __expf(lrelu(sv.x + dv.x));
        float exls = __expf(lrelu(sv.y + dv.y));
        smu += exmu; sls += exls;
        float ex = is_mu ? exmu : exls;
        float4 h = ((const float4*)(g_h23 + (size_t)src * 32))[q];
        fma4(acc, ex, h);
    }
    int total = n * 16;
    if (is_mu) {
        float inv = __frcp_rn(smu);
        float4 bb = ((const float4*)bmu)[q];
        float4 o;
        o.x = fmaf(acc.x, inv, bb.x); o.y = fmaf(acc.y, inv, bb.y);
        o.z = fmaf(acc.z, inv, bb.z); o.w = fmaf(acc.w, inv, bb.w);
        ((float4*)out)[node * 4 + q] = o;
    } else {
        float inv = __frcp_rn(sls);
        float4 bb = ((const float4*)bls)[q - 4];
        float4 o;
        o.x = fmaf(acc.x, inv, bb.x); o.y = fmaf(acc.y, inv, bb.y);
        o.z = fmaf(acc.z, inv, bb.z); o.w = fmaf(acc.w, inv, bb.w);
        ((float4*)(out + total))[node * 4 + (q - 4)] = o;
    }
}

// ---------------- launch ---------------------------------------------
extern "C" void kernel_launch(void* const* d_in, const int* in_sizes, int n_in,
                              void* d_out, int out_size)
{
    const float* x    = (const float*)d_in[0];
    const void*  ei   = d_in[1];
    const float* W1   = (const float*)d_in[2];
    const float* a1s  = (const float*)d_in[3];
    const float* a1d  = (const float*)d_in[4];
    const float* b1   = (const float*)d_in[5];
    const float* Wmu  = (const float*)d_in[6];
    const float* amus = (const float*)d_in[7];
    const float* amud = (const float*)d_in[8];
    const float* bmu  = (const float*)d_in[9];
    const float* Wls  = (const float*)d_in[10];
    const float* alss = (const float*)d_in[11];
    const float* alsd = (const float*)d_in[12];
    const float* bls  = (const float*)d_in[13];

    int n     = in_sizes[0] / 128;      // 100000
    int emain = in_sizes[1] / 2;        // 1600000
    int etot  = emain + n;
    int nblk  = (n + 1023) / 1024;      // scan blocks
    float* out = (float*)d_out;

    k_detect<<<1, 256>>>((const unsigned int*)ei, emain);
    k_prep<<<2048, 256>>>(ei, emain, n);
    k_gemm1<<<(n + 63) / 64, 256>>>(x, W1, a1s, a1d, n);
    k_hist<<<(etot + 255) / 256, 256>>>(etot);
    k_scanA<<<nblk, 256>>>(n);
    k_scanB<<<1, 128>>>(nblk);
    k_scanC<<<nblk, 256>>>(n, etot);
    k_scatter<<<(etot + 255) / 256, 256>>>(etot);
    k_gather1<<<(n * 8 + 255) / 256, 256>>>(b1, n);
    k_node2<<<(n + 31) / 32, 256>>>(Wmu, amus, amud, Wls, alss, alsd, n);
    k_gather23<<<(n * 8 + 255) / 256, 256>>>(bmu, bls, out, n);
}

// round 8
// speedup vs baseline: 4.4783x; 1.0451x over previous
#include <cuda_runtime.h>

// ---------------- problem constants (from reference) ----------------
#define NMAX   100000
#define EMAX   1700032
#define NEG_SLOPE 0.2f

__device__ __forceinline__ void fma4(float4& acc, float s, const float4& wv) {
    acc.x = fmaf(s, wv.x, acc.x); acc.y = fmaf(s, wv.y, acc.y);
    acc.z = fmaf(s, wv.z, acc.z); acc.w = fmaf(s, wv.w, acc.w);
}
__device__ __forceinline__ float lrelu(float v) {
    return (v > 0.0f) ? v : NEG_SLOPE * v;
}

// ---------------- scratch (device globals) --------------------------
__device__ __align__(16) float g_hlin1[NMAX * 32];   // x@W1 (pre-bias)
__device__ float g_as1[NMAX];
__device__ float g_ad1[NMAX];

__device__ __align__(16) float g_h23[NMAX * 32];     // interleaved mu|ls
__device__ __align__(8)  float g_src23[NMAX * 2];
__device__ __align__(8)  float g_dst23[NMAX * 2];

__device__ __align__(8)  int2  g_edges[EMAX];
__device__ int   g_deg[NMAX];
__device__ int   g_off[NMAX + 1];
__device__ int   g_cur[NMAX];
__device__ int   g_bsum[128];
__device__ int   g_csr[EMAX];        // src ids grouped by dst
__device__ int   g_is64;

// ---------------- CSR build -----------------------------------------

__global__ void k_detect(const unsigned int* __restrict__ p, int emain) {
    __shared__ int bad;
    if (threadIdx.x == 0) bad = 0;
    __syncthreads();
    int cnt = 2 * emain; if (cnt > 8192) cnt = 8192;
    for (int i = 1 + 2 * threadIdx.x; i < cnt; i += 2 * blockDim.x)
        if (p[i] != 0u) bad = 1;
    __syncthreads();
    if (threadIdx.x == 0) g_is64 = bad ? 0 : 1;
}

__global__ __launch_bounds__(256) void k_zerodeg(int n) {
    int i = blockIdx.x * blockDim.x + threadIdx.x;
    int stride = gridDim.x * blockDim.x;
    for (int j = i; j < n; j += stride) g_deg[j] = 0;
}

// decode edges (+ self loops) AND accumulate degree histogram
__global__ __launch_bounds__(256) void k_prep(const void* __restrict__ ei,
                                              int emain, int n) {
    int etot = emain + n;
    int stride = gridDim.x * blockDim.x;
    int tid0 = blockIdx.x * blockDim.x + threadIdx.x;
    int is64 = g_is64;
    for (int e = tid0; e < etot; e += stride) {
        int s, d;
        if (e >= emain) { s = d = e - emain; }
        else if (is64) {
            const long long* p = (const long long*)ei;
            s = (int)p[e]; d = (int)p[emain + e];
        } else {
            const int* p = (const int*)ei;
            s = p[e]; d = p[emain + e];
        }
        g_edges[e] = make_int2(s, d);
        atomicAdd(&g_deg[d], 1);
    }
}

// block-level exclusive scan: 1024 elems/block, 4/thread
__global__ __launch_bounds__(256) void k_scanA(int n) {
    __shared__ int ts[256];
    int b = blockIdx.x, tid = threadIdx.x;
    int base = b * 1024 + tid * 4;
    int v0 = (base + 0 < n) ? g_deg[base + 0] : 0;
    int v1 = (base + 1 < n) ? g_deg[base + 1] : 0;
    int v2 = (base + 2 < n) ? g_deg[base + 2] : 0;
    int v3 = (base + 3 < n) ? g_deg[base + 3] : 0;
    int tsum = v0 + v1 + v2 + v3;
    ts[tid] = tsum;
    __syncthreads();
    #pragma unroll
    for (int d = 1; d < 256; d <<= 1) {
        int t = (tid >= d) ? ts[tid - d] : 0;
        __syncthreads();
        ts[tid] += t;
        __syncthreads();
    }
    int excl = (tid > 0) ? ts[tid - 1] : 0;
    int run = excl;
    if (base + 0 < n) { g_off[base + 0] = run; } run += v0;
    if (base + 1 < n) { g_off[base + 1] = run; } run += v1;
    if (base + 2 < n) { g_off[base + 2] = run; } run += v2;
    if (base + 3 < n) { g_off[base + 3] = run; } run += v3;
    if (tid == 255) g_bsum[b] = ts[255];
}

__global__ void k_scanB(int nblk) {
    __shared__ int s[128];
    int tid = threadIdx.x;
    s[tid] = (tid < nblk) ? g_bsum[tid] : 0;
    __syncthreads();
    #pragma unroll
    for (int d = 1; d < 128; d <<= 1) {
        int t = (tid >= d) ? s[tid - d] : 0;
        __syncthreads();
        s[tid] += t;
        __syncthreads();
    }
    if (tid < nblk) g_bsum[tid] = (tid > 0) ? s[tid - 1] : 0;
}

__global__ __launch_bounds__(256) void k_scanC(int n, int etot) {
    int b = blockIdx.x, tid = threadIdx.x;
    int add = g_bsum[b];
    int base = b * 1024 + tid * 4;
    #pragma unroll
    for (int j = 0; j < 4; j++) {
        int i = base + j;
        if (i < n) {
            int v = g_off[i] + add;
            g_off[i] = v;
            g_cur[i] = v;
        }
    }
    if (b == 0 && tid == 0) g_off[n] = etot;
}

__global__ __launch_bounds__(256) void k_scatter(int etot) {
    int stride = gridDim.x * blockDim.x;
    for (int e = blockIdx.x * blockDim.x + threadIdx.x; e < etot; e += stride) {
        int2 ed = g_edges[e];
        int pos = atomicAdd(&g_cur[ed.y], 1);
        g_csr[pos] = ed.x;
    }
}

// ---------------- compute kernels -----------------------------------

// hlin1 = x @ W1 ; attention dots. 64 nodes/block, 2 nodes/thread.
__global__ __launch_bounds__(256) void k_gemm1(
    const float* __restrict__ x, const float* __restrict__ W1,
    const float* __restrict__ a1s, const float* __restrict__ a1d, int n)
{
    __shared__ float4 Ws4[128 * 8];
    __shared__ float4 xs4[64 * 33];
    __shared__ float4 as4[8], ad4[8];
    int tid = threadIdx.x;
    const float4* W4 = (const float4*)W1;
    for (int i = tid; i < 1024; i += 256) Ws4[i] = W4[i];
    if (tid < 8)        as4[tid]     = ((const float4*)a1s)[tid];
    else if (tid < 16)  ad4[tid - 8] = ((const float4*)a1d)[tid - 8];

    int base = blockIdx.x * 64;
    const float4* xg = (const float4*)x + (size_t)base * 32;
    int navail = n - base; if (navail > 64) navail = 64;
    for (int f = tid; f < navail * 32; f += 256) {
        int node = f >> 5, j = f & 31;
        xs4[node * 33 + j] = xg[f];
    }
    __syncthreads();

    int warp = tid >> 5, lane = tid & 31;
    int pair = lane >> 3, q = lane & 7;
    int nodeL0 = warp * 8 + pair * 2;
    int nodeL1 = nodeL0 + 1;
    int node0 = base + nodeL0, node1 = base + nodeL1;

    const float4* xr0 = xs4 + nodeL0 * 33;
    const float4* xr1 = xs4 + nodeL1 * 33;
    float4 acc0 = make_float4(0.f, 0.f, 0.f, 0.f);
    float4 acc1 = make_float4(0.f, 0.f, 0.f, 0.f);
    #pragma unroll 2
    for (int k4 = 0; k4 < 32; k4++) {
        float4 xv0 = xr0[k4];
        float4 xv1 = xr1[k4];
        float4 w0 = Ws4[(k4 * 4 + 0) * 8 + q];
        float4 w1 = Ws4[(k4 * 4 + 1) * 8 + q];
        float4 w2 = Ws4[(k4 * 4 + 2) * 8 + q];
        float4 w3 = Ws4[(k4 * 4 + 3) * 8 + q];
        fma4(acc0, xv0.x, w0); fma4(acc1, xv1.x, w0);
        fma4(acc0, xv0.y, w1); fma4(acc1, xv1.y, w1);
        fma4(acc0, xv0.z, w2); fma4(acc1, xv1.z, w2);
        fma4(acc0, xv0.w, w3); fma4(acc1, xv1.w, w3);
    }

    float4 av = as4[q], dv = ad4[q];
    float ts0 = acc0.x * av.x + acc0.y * av.y + acc0.z * av.z + acc0.w * av.w;
    float td0 = acc0.x * dv.x + acc0.y * dv.y + acc0.z * dv.z + acc0.w * dv.w;
    float ts1 = acc1.x * av.x + acc1.y * av.y + acc1.z * av.z + acc1.w * av.w;
    float td1 = acc1.x * dv.x + acc1.y * dv.y + acc1.z * dv.z + acc1.w * dv.w;
    #pragma unroll
    for (int off = 4; off >= 1; off >>= 1) {
        ts0 += __shfl_xor_sync(0xffffffffu, ts0, off);
        td0 += __shfl_xor_sync(0xffffffffu, td0, off);
        ts1 += __shfl_xor_sync(0xffffffffu, ts1, off);
        td1 += __shfl_xor_sync(0xffffffffu, td1, off);
    }
    if (node0 < n) {
        ((float4*)(g_hlin1 + (size_t)node0 * 32))[q] = acc0;
        if (q == 0) { g_as1[node0] = ts0; g_ad1[node0] = td0; }
    }
    if (node1 < n) {
        ((float4*)(g_hlin1 + (size_t)node1 * 32))[q] = acc1;
        if (q == 0) { g_as1[node1] = ts1; g_ad1[node1] = td1; }
    }
}

// Fused layer-1 gather + layer-2 linear:
// h1 = relu(gather-softmax + b1) computed in-register (never stored),
// h23 = h1 @ [Wmu|Wls] via 8-lane shuffle matmul, plus attention dots.
__global__ __launch_bounds__(256) void k_gather1(
    const float* __restrict__ b1,
    const float* __restrict__ Wmu, const float* __restrict__ amus,
    const float* __restrict__ amud,
    const float* __restrict__ Wls, const float* __restrict__ alss,
    const float* __restrict__ alsd, int n)
{
    __shared__ float Wcat[32 * 32];      // [k][c]: c<16 mu, c>=16 ls
    __shared__ float4 b1s4[8];
    __shared__ float4 srcv4[8], dstv4[8];
    int tid = threadIdx.x;
    for (int i = tid; i < 1024; i += 256) {
        int k = i >> 5, c = i & 31;
        Wcat[i] = (c < 16) ? Wmu[k * 16 + c] : Wls[k * 16 + (c - 16)];
    }
    if (tid < 8) b1s4[tid] = ((const float4*)b1)[tid];
    if (tid < 32) {
        float sv = (tid < 16) ? amus[tid] : alss[tid - 16];
        float dv = (tid < 16) ? amud[tid] : alsd[tid - 16];
        ((float*)srcv4)[tid] = sv;
        ((float*)dstv4)[tid] = dv;
    }
    __syncthreads();

    int t = blockIdx.x * blockDim.x + tid;
    int node = t >> 3;
    bool act = (node < n);
    if (!act) node = n - 1;
    int lane = tid & 31;
    int q = lane & 7;
    int gbase = lane & 24;               // 8-lane group base within warp

    float ad = g_ad1[node];
    int off0 = g_off[node], off1 = g_off[node + 1];
    float4 acc = make_float4(0.f, 0.f, 0.f, 0.f);
    float s = 0.0f;
    #pragma unroll 4
    for (int i = off0; i < off1; i++) {
        int src = g_csr[i];
        float ex = __expf(lrelu(g_as1[src] + ad));
        float4 h = ((const float4*)(g_hlin1 + (size_t)src * 32))[q];
        fma4(acc, ex, h);
        s += ex;
    }
    float inv = __frcp_rn(s);
    float4 bb = b1s4[q];
    float4 h1;
    h1.x = fmaxf(fmaf(acc.x, inv, bb.x), 0.f);
    h1.y = fmaxf(fmaf(acc.y, inv, bb.y), 0.f);
    h1.z = fmaxf(fmaf(acc.z, inv, bb.z), 0.f);
    h1.w = fmaxf(fmaf(acc.w, inv, bb.w), 0.f);

    // 32x32 matmul: shuffle-broadcast h1 across the 8-lane group.
    const float4* Wc4 = (const float4*)Wcat;
    float4 o = make_float4(0.f, 0.f, 0.f, 0.f);
    #pragma unroll
    for (int r = 0; r < 8; r++) {
        float hx = __shfl_sync(0xffffffffu, h1.x, gbase + r);
        float hy = __shfl_sync(0xffffffffu, h1.y, gbase + r);
        float hz = __shfl_sync(0xffffffffu, h1.z, gbase + r);
        float hw = __shfl_sync(0xffffffffu, h1.w, gbase + r);
        fma4(o, hx, Wc4[(4 * r + 0) * 8 + q]);
        fma4(o, hy, Wc4[(4 * r + 1) * 8 + q]);
        fma4(o, hz, Wc4[(4 * r + 2) * 8 + q]);
        fma4(o, hw, Wc4[(4 * r + 3) * 8 + q]);
    }

    float4 av = srcv4[q], dv = dstv4[q];
    float ts = o.x * av.x + o.y * av.y + o.z * av.z + o.w * av.w;
    float td = o.x * dv.x + o.y * dv.y + o.z * dv.z + o.w * dv.w;
    #pragma unroll
    for (int off = 2; off >= 1; off >>= 1) {   // reduce within 4-lane half
        ts += __shfl_xor_sync(0xffffffffu, ts, off);
        td += __shfl_xor_sync(0xffffffffu, td, off);
    }
    if (act) {
        ((float4*)(g_h23 + (size_t)node * 32))[q] = o;
        if (q == 0) { g_src23[2 * node + 0] = ts; g_dst23[2 * node + 0] = td; }
        if (q == 4) { g_src23[2 * node + 1] = ts; g_dst23[2 * node + 1] = td; }
    }
}

// Layer-2 gather (mu+ls fused): 8 lanes per dst node; writes final output.
__global__ __launch_bounds__(256) void k_gather23(
    const float* __restrict__ bmu, const float* __restrict__ bls,
    float* __restrict__ out, int n)
{
    int t = blockIdx.x * blockDim.x + threadIdx.x;
    int node = t >> 3;
    if (node >= n) return;
    int q = t & 7;
    float2 dv = *(const float2*)(g_dst23 + 2 * node);
    int off0 = g_off[node], off1 = g_off[node + 1];
    float4 acc = make_float4(0.f, 0.f, 0.f, 0.f);
    float smu = 0.0f, sls = 0.0f;
    bool is_mu = (q < 4);
    #pragma unroll 4
    for (int i = off0; i < off1; i++) {
        int src = g_csr[i];
        float2 sv = *(const float2*)(g_src23 + 2 * src);
        float exmu = __expf(lrelu(sv.x + dv.x));
        float exls = __expf(lrelu(sv.y + dv.y));
        smu += exmu; sls += exls;
        float ex = is_mu ? exmu : exls;
        float4 h = ((const float4*)(g_h23 + (size_t)src * 32))[q];
        fma4(acc, ex, h);
    }
    int total = n * 16;
    if (is_mu) {
        float inv = __frcp_rn(smu);
        float4 bb = ((const float4*)bmu)[q];
        float4 o;
        o.x = fmaf(acc.x, inv, bb.x); o.y = fmaf(acc.y, inv, bb.y);
        o.z = fmaf(acc.z, inv, bb.z); o.w = fmaf(acc.w, inv, bb.w);
        ((float4*)out)[node * 4 + q] = o;
    } else {
        float inv = __frcp_rn(sls);
        float4 bb = ((const float4*)bls)[q - 4];
        float4 o;
        o.x = fmaf(acc.x, inv, bb.x); o.y = fmaf(acc.y, inv, bb.y);
        o.z = fmaf(acc.z, inv, bb.z); o.w = fmaf(acc.w, inv, bb.w);
        ((float4*)(out + total))[node * 4 + (q - 4)] = o;
    }
}

// ---------------- launch ---------------------------------------------
extern "C" void kernel_launch(void* const* d_in, const int* in_sizes, int n_in,
                              void* d_out, int out_size)
{
    const float* x    = (const float*)d_in[0];
    const void*  ei   = d_in[1];
    const float* W1   = (const float*)d_in[2];
    const float* a1s  = (const float*)d_in[3];
    const float* a1d  = (const float*)d_in[4];
    const float* b1   = (const float*)d_in[5];
    const float* Wmu  = (const float*)d_in[6];
    const float* amus = (const float*)d_in[7];
    const float* amud = (const float*)d_in[8];
    const float* bmu  = (const float*)d_in[9];
    const float* Wls  = (const float*)d_in[10];
    const float* alss = (const float*)d_in[11];
    const float* alsd = (const float*)d_in[12];
    const float* bls  = (const float*)d_in[13];

    int n     = in_sizes[0] / 128;      // 100000
    int emain = in_sizes[1] / 2;        // 1600000
    int etot  = emain + n;
    int nblk  = (n + 1023) / 1024;      // scan blocks
    float* out = (float*)d_out;

    k_detect<<<1, 256>>>((const unsigned int*)ei, emain);
    k_zerodeg<<<512, 256>>>(n);
    k_prep<<<2048, 256>>>(ei, emain, n);
    k_gemm1<<<(n + 63) / 64, 256>>>(x, W1, a1s, a1d, n);
    k_scanA<<<nblk, 256>>>(n);
    k_scanB<<<1, 128>>>(nblk);
    k_scanC<<<nblk, 256>>>(n, etot);
    k_scatter<<<(etot + 255) / 256, 256>>>(etot);
    k_gather1<<<(n * 8 + 255) / 256, 256>>>(b1, Wmu, amus, amud,
                                            Wls, alss, alsd, n);
    k_gather23<<<(n * 8 + 255) / 256, 256>>>(bmu, bls, out, n);
}